// round 2
// baseline (speedup 1.0000x reference)
#include <cuda_runtime.h>
#include <cuda_bf16.h>
#include <math.h>

// ---- problem constants (gpt-small) ----
#define Lc 8
#define Hc 8
#define Cc 256
#define Vc 128
#define Tc 1024
#define Bc 32
#define Dh 32
#define FFc 1024
#define NTOK (Bc * Tc)   // 32768

// ---- scratch (device globals; no allocation allowed) ----
__device__ float g_x[(size_t)NTOK * Cc];     // residual stream
__device__ float g_ln[(size_t)NTOK * Cc];    // LN output / attention y
__device__ float g_qkv[(size_t)NTOK * 3 * Cc];
__device__ float g_ff[(size_t)NTOK * FFc];   // fc (gelu) output

// ------------------------------------------------------------------
// Embedding: x[n,c] = tok_emb[idx[n], c] + pos_emb[n % T, c]
// ------------------------------------------------------------------
__global__ void embed_kernel(const int* __restrict__ idx,
                             const float* __restrict__ tok,
                             const float* __restrict__ pos,
                             float* __restrict__ x) {
    int n = blockIdx.x;
    int c = threadIdx.x;
    int token = idx[n];
    x[(size_t)n * Cc + c] = tok[(size_t)token * Cc + c] + pos[(size_t)(n % Tc) * Cc + c];
}

// ------------------------------------------------------------------
// LayerNorm: one block (256 threads) per row of 256 elements
// ------------------------------------------------------------------
__global__ void ln_kernel(const float* __restrict__ x,
                          const float* __restrict__ g,
                          const float* __restrict__ b,
                          float* __restrict__ out) {
    int row = blockIdx.x;
    int tid = threadIdx.x;
    int w = tid >> 5, lane = tid & 31;
    float v = x[(size_t)row * Cc + tid];

    __shared__ float sm[8];
    __shared__ float sm2[8];

    float s = v;
#pragma unroll
    for (int o = 16; o; o >>= 1) s += __shfl_xor_sync(0xffffffffu, s, o);
    if (lane == 0) sm[w] = s;
    __syncthreads();
    float tot = 0.f;
#pragma unroll
    for (int i = 0; i < 8; i++) tot += sm[i];
    float mean = tot * (1.0f / Cc);

    float d = v - mean;
    float q = d * d;
#pragma unroll
    for (int o = 16; o; o >>= 1) q += __shfl_xor_sync(0xffffffffu, q, o);
    if (lane == 0) sm2[w] = q;
    __syncthreads();
    float vtot = 0.f;
#pragma unroll
    for (int i = 0; i < 8; i++) vtot += sm2[i];
    float var = vtot * (1.0f / Cc);

    out[(size_t)row * Cc + tid] = d * rsqrtf(var + 1e-5f) * g[tid] + b[tid];
}

// ------------------------------------------------------------------
// GEMM: out[M,N] = A[M,K] @ B[K,N] (+bias) (+residual) (+gelu)
// BM=128, BN=64, BK=16, 256 threads, 8x4 microtile.
// All shapes here are exact multiples of the tile sizes.
// MODE: 0 = bias only, 1 = bias + residual, 2 = bias + gelu
// ------------------------------------------------------------------
__device__ __forceinline__ float gelu_f(float x) {
    float x3 = x * x * x;
    return 0.5f * x * (1.0f + tanhf(0.7978845608028654f * (x + 0.044715f * x3)));
}

#define GBM 128
#define GBN 64
#define GBK 16

template <int MODE>
__global__ __launch_bounds__(256) void gemm_kernel(
    const float* __restrict__ A, const float* __restrict__ B,
    const float* __restrict__ bias, const float* __restrict__ res,
    float* __restrict__ out, int M, int N, int K) {
    __shared__ float As[GBK][GBM + 4];
    __shared__ float Bs[GBK][GBN];

    int tid = threadIdx.x;
    int bm = blockIdx.y * GBM;
    int bn = blockIdx.x * GBN;
    int tx = tid & 15;       // N direction (0..15) -> 4 cols each
    int ty = tid >> 4;       // M direction (0..15) -> 8 rows each

    float acc[8][4] = {};

    for (int k0 = 0; k0 < K; k0 += GBK) {
        // load A tile: 128x16 floats -> 2 float4 per thread
#pragma unroll
        for (int i = 0; i < 2; i++) {
            int id = tid + i * 256;
            int m = id >> 2;
            int kk = (id & 3) << 2;
            float4 a = *(const float4*)(A + (size_t)(bm + m) * K + k0 + kk);
            As[kk + 0][m] = a.x;
            As[kk + 1][m] = a.y;
            As[kk + 2][m] = a.z;
            As[kk + 3][m] = a.w;
        }
        // load B tile: 16x64 floats -> 1 float4 per thread
        {
            int kk = tid >> 4;
            int n = (tid & 15) << 2;
            *(float4*)(&Bs[kk][n]) = *(const float4*)(B + (size_t)(k0 + kk) * N + bn + n);
        }
        __syncthreads();

#pragma unroll
        for (int kk = 0; kk < GBK; kk++) {
            float a[8], bvals[4];
#pragma unroll
            for (int i = 0; i < 8; i++) a[i] = As[kk][ty * 8 + i];
#pragma unroll
            for (int j = 0; j < 4; j++) bvals[j] = Bs[kk][tx * 4 + j];
#pragma unroll
            for (int i = 0; i < 8; i++)
#pragma unroll
                for (int j = 0; j < 4; j++) acc[i][j] += a[i] * bvals[j];
        }
        __syncthreads();
    }

#pragma unroll
    for (int i = 0; i < 8; i++) {
        int m = bm + ty * 8 + i;
#pragma unroll
        for (int j = 0; j < 4; j++) {
            int n = bn + tx * 4 + j;
            float v = acc[i][j];
            if (bias) v += bias[n];
            if (MODE == 1) v += res[(size_t)m * N + n];
            if (MODE == 2) v = gelu_f(v);
            out[(size_t)m * N + n] = v;
        }
    }
}

// ------------------------------------------------------------------
// Attention: one block (128 threads = 4 warps) per (b, h, q).
// qkv layout: [n, 3C] with q at [h*32], k at [C + h*32], v at [2C + h*32].
// ------------------------------------------------------------------
__global__ __launch_bounds__(128) void attn_kernel(const float* __restrict__ qkv,
                                                   float* __restrict__ y) {
    int t = blockIdx.x, h = blockIdx.y, b = blockIdx.z;
    int n = b * Tc + t;
    int tid = threadIdx.x;
    int lane = tid & 31, w = tid >> 5;

    __shared__ float sq[32];
    __shared__ float sc[Tc];
    __shared__ float red[8];
    __shared__ float accs[4][32];

    if (tid < 32) sq[tid] = qkv[(size_t)n * 3 * Cc + h * Dh + tid];
    __syncthreads();

    int nk = t + 1;
    const float scale = 0.17677669529663687f;  // 1/sqrt(32)

    // pass 1: scores (one key per warp per iter)
    for (int k = w; k < nk; k += 4) {
        const float* krow = qkv + (size_t)(b * Tc + k) * 3 * Cc + Cc + h * Dh;
        float p = sq[lane] * krow[lane];
#pragma unroll
        for (int o = 16; o; o >>= 1) p += __shfl_xor_sync(0xffffffffu, p, o);
        if (lane == 0) sc[k] = p * scale;
    }
    __syncthreads();

    // block max
    float m = -INFINITY;
    for (int k = tid; k < nk; k += 128) m = fmaxf(m, sc[k]);
#pragma unroll
    for (int o = 16; o; o >>= 1) m = fmaxf(m, __shfl_xor_sync(0xffffffffu, m, o));
    if (lane == 0) red[w] = m;
    __syncthreads();
    m = fmaxf(fmaxf(red[0], red[1]), fmaxf(red[2], red[3]));
    __syncthreads();

    // exp + block sum
    float s = 0.f;
    for (int k = tid; k < nk; k += 128) {
        float e = __expf(sc[k] - m);
        sc[k] = e;
        s += e;
    }
#pragma unroll
    for (int o = 16; o; o >>= 1) s += __shfl_xor_sync(0xffffffffu, s, o);
    if (lane == 0) red[4 + w] = s;
    __syncthreads();
    float inv = 1.0f / (red[4] + red[5] + red[6] + red[7]);

    // pass 2: out[d] = sum_k p[k] * V[k, d]   (lane = d)
    float acc = 0.f;
    for (int k = w; k < nk; k += 4) {
        const float* vrow = qkv + (size_t)(b * Tc + k) * 3 * Cc + 2 * Cc + h * Dh;
        acc += sc[k] * vrow[lane];
    }
    accs[w][lane] = acc;
    __syncthreads();
    if (w == 0) {
        float o = (accs[0][lane] + accs[1][lane] + accs[2][lane] + accs[3][lane]) * inv;
        y[(size_t)n * Cc + h * Dh + lane] = o;
    }
}

// ------------------------------------------------------------------
// Host orchestration
// ------------------------------------------------------------------
extern "C" void kernel_launch(void* const* d_in, const int* in_sizes, int n_in,
                              void* d_out, int out_size) {
    const int*   idx    = (const int*)d_in[0];
    const float* tok    = (const float*)d_in[1];
    const float* pos    = (const float*)d_in[2];
    const float* ln1_g  = (const float*)d_in[3];
    const float* ln1_b  = (const float*)d_in[4];
    const float* wqkv   = (const float*)d_in[5];
    const float* bqkv   = (const float*)d_in[6];
    const float* wo     = (const float*)d_in[7];
    const float* bo     = (const float*)d_in[8];
    const float* ln2_g  = (const float*)d_in[9];
    const float* ln2_b  = (const float*)d_in[10];
    const float* wfc    = (const float*)d_in[11];
    const float* bfc    = (const float*)d_in[12];
    const float* wpr    = (const float*)d_in[13];
    const float* bpr    = (const float*)d_in[14];
    const float* lnf_g  = (const float*)d_in[15];
    const float* lnf_b  = (const float*)d_in[16];
    const float* w_lm   = (const float*)d_in[17];
    float* out = (float*)d_out;

    float *px, *pln, *pqkv, *pff;
    cudaGetSymbolAddress((void**)&px, g_x);
    cudaGetSymbolAddress((void**)&pln, g_ln);
    cudaGetSymbolAddress((void**)&pqkv, g_qkv);
    cudaGetSymbolAddress((void**)&pff, g_ff);

    // embedding
    embed_kernel<<<NTOK, Cc>>>(idx, tok, pos, px);

    dim3 gemm_block(256);

    for (int l = 0; l < Lc; l++) {
        const float* Wq = wqkv + (size_t)l * Cc * 3 * Cc;
        const float* bq = bqkv + (size_t)l * 3 * Cc;
        const float* Wo = wo + (size_t)l * Cc * Cc;
        const float* bo_ = bo + (size_t)l * Cc;
        const float* Wf = wfc + (size_t)l * Cc * FFc;
        const float* bf = bfc + (size_t)l * FFc;
        const float* Wp = wpr + (size_t)l * FFc * Cc;
        const float* bp = bpr + (size_t)l * Cc;

        // ln1
        ln_kernel<<<NTOK, Cc>>>(px, ln1_g + (size_t)l * Cc, ln1_b + (size_t)l * Cc, pln);
        // qkv = ln @ Wq + bq   [32768, 768]
        {
            dim3 grid((3 * Cc) / GBN, NTOK / GBM);
            gemm_kernel<0><<<grid, gemm_block>>>(pln, Wq, bq, nullptr, pqkv, NTOK, 3 * Cc, Cc);
        }
        // attention -> y into pln
        {
            dim3 grid(Tc, Hc, Bc);
            attn_kernel<<<grid, 128>>>(pqkv, pln);
        }
        // x = x + y @ Wo + bo
        {
            dim3 grid(Cc / GBN, NTOK / GBM);
            gemm_kernel<1><<<grid, gemm_block>>>(pln, Wo, bo_, px, px, NTOK, Cc, Cc);
        }
        // ln2
        ln_kernel<<<NTOK, Cc>>>(px, ln2_g + (size_t)l * Cc, ln2_b + (size_t)l * Cc, pln);
        // ff = gelu(ln @ Wf + bf)   [32768, 1024]
        {
            dim3 grid(FFc / GBN, NTOK / GBM);
            gemm_kernel<2><<<grid, gemm_block>>>(pln, Wf, bf, nullptr, pff, NTOK, FFc, Cc);
        }
        // x = x + ff @ Wp + bp
        {
            dim3 grid(Cc / GBN, NTOK / GBM);
            gemm_kernel<1><<<grid, gemm_block>>>(pff, Wp, bp, px, px, NTOK, Cc, FFc);
        }
    }

    // final ln
    ln_kernel<<<NTOK, Cc>>>(px, lnf_g, lnf_b, pln);
    // logits = ln @ w_lm   [32768, 128], no bias
    {
        dim3 grid(Vc / GBN, NTOK / GBM);
        gemm_kernel<0><<<grid, gemm_block>>>(pln, w_lm, nullptr, nullptr, out, NTOK, Vc, Cc);
    }
}

// round 3
// speedup vs baseline: 1.1465x; 1.1465x over previous
#include <cuda_runtime.h>
#include <cuda_bf16.h>
#include <math.h>
#include <stdint.h>

// ---- problem constants (gpt-small) ----
#define Lc 8
#define Hc 8
#define Cc 256
#define Vc 128
#define Tc 1024
#define Bc 32
#define Dh 32
#define FFc 1024
#define NTOK (Bc * Tc)   // 32768

// ---- scratch (device globals; no allocation allowed) ----
__device__ float g_x[(size_t)NTOK * Cc];     // residual stream
__device__ float g_ln[(size_t)NTOK * Cc];    // LN output / attention y (tf32-rounded)
__device__ float g_qkv[(size_t)NTOK * 3 * Cc];
__device__ float g_ff[(size_t)NTOK * FFc];   // fc (gelu) output (tf32-rounded)

// tf32-rounded weights: qkv | wo | wfc | wpr | w_lm
#define W_QKV_OFF 0
#define W_O_OFF   (W_QKV_OFF + (size_t)Lc * Cc * 3 * Cc)          // 1572864
#define W_FC_OFF  (W_O_OFF   + (size_t)Lc * Cc * Cc)              // +524288
#define W_PR_OFF  (W_FC_OFF  + (size_t)Lc * Cc * FFc)             // +2097152
#define W_LM_OFF  (W_PR_OFF  + (size_t)Lc * FFc * Cc)             // +2097152
#define W_TOTAL   (W_LM_OFF  + (size_t)Cc * Vc)                   // +32768
__device__ float g_w[W_TOTAL];

// ------------------------------------------------------------------
// helpers
// ------------------------------------------------------------------
__device__ __forceinline__ float to_tf32(float x) {
    uint32_t u;
    asm("cvt.rna.tf32.f32 %0, %1;" : "=r"(u) : "f"(x));
    return __uint_as_float(u);
}

__device__ __forceinline__ float gelu_f(float x) {
    float x3 = x * x * x;
    return 0.5f * x * (1.0f + tanhf(0.7978845608028654f * (x + 0.044715f * x3)));
}

__device__ __forceinline__ uint32_t smem_u32(const void* p) {
    uint32_t a;
    asm("{.reg .u64 t; cvta.to.shared.u64 t, %1; cvt.u32.u64 %0, t;}" : "=r"(a) : "l"(p));
    return a;
}

__device__ __forceinline__ void cp16(uint32_t dst, const void* src) {
    asm volatile("cp.async.cg.shared.global [%0], [%1], 16;\n" :: "r"(dst), "l"(src));
}

__device__ __forceinline__ void mma_tf32(float* c, const uint32_t* a, const uint32_t* b) {
    asm volatile(
        "mma.sync.aligned.m16n8k8.row.col.f32.tf32.tf32.f32 "
        "{%0,%1,%2,%3}, {%4,%5,%6,%7}, {%8,%9}, {%0,%1,%2,%3};\n"
        : "+f"(c[0]), "+f"(c[1]), "+f"(c[2]), "+f"(c[3])
        : "r"(a[0]), "r"(a[1]), "r"(a[2]), "r"(a[3]), "r"(b[0]), "r"(b[1]));
}

// ------------------------------------------------------------------
// weight tf32-rounding (once per call, off the hot path)
// ------------------------------------------------------------------
__global__ void cvt_kernel(const float* __restrict__ in, float* __restrict__ out, int n) {
    for (int i = blockIdx.x * blockDim.x + threadIdx.x; i < n; i += gridDim.x * blockDim.x)
        out[i] = to_tf32(in[i]);
}

// ------------------------------------------------------------------
// Embedding
// ------------------------------------------------------------------
__global__ void embed_kernel(const int* __restrict__ idx,
                             const float* __restrict__ tok,
                             const float* __restrict__ pos,
                             float* __restrict__ x) {
    int n = blockIdx.x;
    int c = threadIdx.x;
    int token = idx[n];
    x[(size_t)n * Cc + c] = tok[(size_t)token * Cc + c] + pos[(size_t)(n % Tc) * Cc + c];
}

// ------------------------------------------------------------------
// LayerNorm (output tf32-rounded: it only ever feeds GEMM-A)
// ------------------------------------------------------------------
__global__ void ln_kernel(const float* __restrict__ x,
                          const float* __restrict__ g,
                          const float* __restrict__ b,
                          float* __restrict__ out) {
    int row = blockIdx.x;
    int tid = threadIdx.x;
    int w = tid >> 5, lane = tid & 31;
    float v = x[(size_t)row * Cc + tid];

    __shared__ float sm[8];
    __shared__ float sm2[8];

    float s = v;
#pragma unroll
    for (int o = 16; o; o >>= 1) s += __shfl_xor_sync(0xffffffffu, s, o);
    if (lane == 0) sm[w] = s;
    __syncthreads();
    float tot = 0.f;
#pragma unroll
    for (int i = 0; i < 8; i++) tot += sm[i];
    float mean = tot * (1.0f / Cc);

    float d = v - mean;
    float q = d * d;
#pragma unroll
    for (int o = 16; o; o >>= 1) q += __shfl_xor_sync(0xffffffffu, q, o);
    if (lane == 0) sm2[w] = q;
    __syncthreads();
    float vtot = 0.f;
#pragma unroll
    for (int i = 0; i < 8; i++) vtot += sm2[i];
    float var = vtot * (1.0f / Cc);

    out[(size_t)row * Cc + tid] = to_tf32(d * rsqrtf(var + 1e-5f) * g[tid] + b[tid]);
}

// ------------------------------------------------------------------
// Tensor-core GEMM: out[M,N] = A[M,K] @ B[K,N] (+bias) (+res) (+gelu+tf32)
// BM=128 BN=128 BK=16, 256 threads, warp tile 64x32, mma.m16n8k8 tf32.
// A, B are pre-rounded to tf32. MODE: 0=bias, 1=bias+residual, 2=bias+gelu(->tf32)
// ------------------------------------------------------------------
#define BM 128
#define BN 128
#define BK 16
#define ASTRIDE 20    // BK + 4 pad (conflict-free fragment reads)
#define BSTRIDE 136   // BN + 8 pad

template <int MODE>
__global__ __launch_bounds__(256) void gemm_tc(
    const float* __restrict__ A, const float* __restrict__ B,
    const float* __restrict__ bias, const float* __restrict__ res,
    float* __restrict__ out, int M, int N, int K) {
    __shared__ float As[2][BM * ASTRIDE];
    __shared__ float Bs[2][BK * BSTRIDE];

    int tid = threadIdx.x;
    int bm = blockIdx.y * BM;
    int bn = blockIdx.x * BN;
    int lane = tid & 31, wid = tid >> 5;
    int wm = (wid >> 2) * 64;   // warp M offset (0 / 64)
    int wn = (wid & 3) * 32;    // warp N offset (0/32/64/96)
    int grp = lane >> 2, tig = lane & 3;

    float acc[4][4][4];
#pragma unroll
    for (int i = 0; i < 4; i++)
#pragma unroll
        for (int j = 0; j < 4; j++)
#pragma unroll
            for (int k = 0; k < 4; k++) acc[i][j][k] = 0.f;

    uint32_t sA0 = smem_u32(As[0]), sA1 = smem_u32(As[1]);
    uint32_t sB0 = smem_u32(Bs[0]), sB1 = smem_u32(Bs[1]);

    // per-thread copy geometry
    int am = tid >> 2;              // A rows am, am+64 ; k-vec (tid&3)*4
    int ak = (tid & 3) << 2;
    int br = tid >> 5;              // B rows br, br+8 ; n-vec (tid&31)*4
    int bnv = (tid & 31) << 2;

    const float* gA0 = A + (size_t)(bm + am) * K + ak;
    const float* gA1 = A + (size_t)(bm + am + 64) * K + ak;
    const float* gB0 = B + (size_t)br * N + bn + bnv;
    const float* gB1 = B + (size_t)(br + 8) * N + bn + bnv;

    uint32_t dA0 = (uint32_t)((am * ASTRIDE + ak) * 4);
    uint32_t dA1 = (uint32_t)(((am + 64) * ASTRIDE + ak) * 4);
    uint32_t dB0 = (uint32_t)((br * BSTRIDE + bnv) * 4);
    uint32_t dB1 = (uint32_t)(((br + 8) * BSTRIDE + bnv) * 4);

    int KT = K / BK;

    // prologue: tile 0 into buffer 0
    {
        cp16(sA0 + dA0, gA0);
        cp16(sA0 + dA1, gA1);
        cp16(sB0 + dB0, gB0);
        cp16(sB0 + dB1, gB1);
        asm volatile("cp.async.commit_group;\n" ::: "memory");
    }

    int buf = 0;
    for (int kt = 0; kt < KT; kt++) {
        asm volatile("cp.async.wait_group 0;\n" ::: "memory");
        __syncthreads();

        if (kt + 1 < KT) {
            uint32_t a_s = buf ? sA0 : sA1;   // other buffer
            uint32_t b_s = buf ? sB0 : sB1;
            int ko = (kt + 1) * BK;
            cp16(a_s + dA0, gA0 + ko);
            cp16(a_s + dA1, gA1 + ko);
            cp16(b_s + dB0, gB0 + (size_t)ko * N);
            cp16(b_s + dB1, gB1 + (size_t)ko * N);
            asm volatile("cp.async.commit_group;\n" ::: "memory");
        }

        const float* as = As[buf];
        const float* bs = Bs[buf];
#pragma unroll
        for (int kk = 0; kk < 2; kk++) {
            int k0 = kk * 8;
            uint32_t a[4][4], b[4][2];
#pragma unroll
            for (int mi = 0; mi < 4; mi++) {
                int r = wm + mi * 16 + grp;
                a[mi][0] = __float_as_uint(as[r * ASTRIDE + k0 + tig]);
                a[mi][1] = __float_as_uint(as[(r + 8) * ASTRIDE + k0 + tig]);
                a[mi][2] = __float_as_uint(as[r * ASTRIDE + k0 + tig + 4]);
                a[mi][3] = __float_as_uint(as[(r + 8) * ASTRIDE + k0 + tig + 4]);
            }
#pragma unroll
            for (int ni = 0; ni < 4; ni++) {
                int c = wn + ni * 8 + grp;
                b[ni][0] = __float_as_uint(bs[(k0 + tig) * BSTRIDE + c]);
                b[ni][1] = __float_as_uint(bs[(k0 + tig + 4) * BSTRIDE + c]);
            }
#pragma unroll
            for (int mi = 0; mi < 4; mi++)
#pragma unroll
                for (int ni = 0; ni < 4; ni++)
                    mma_tf32(acc[mi][ni], a[mi], b[ni]);
        }
        buf ^= 1;
    }

    // epilogue
#pragma unroll
    for (int mi = 0; mi < 4; mi++) {
        int r0 = bm + wm + mi * 16 + grp;
#pragma unroll
        for (int ni = 0; ni < 4; ni++) {
            int c0 = bn + wn + ni * 8 + 2 * tig;
            float v00 = acc[mi][ni][0], v01 = acc[mi][ni][1];
            float v10 = acc[mi][ni][2], v11 = acc[mi][ni][3];
            if (bias) {
                float b0 = bias[c0], b1 = bias[c0 + 1];
                v00 += b0; v01 += b1; v10 += b0; v11 += b1;
            }
            if (MODE == 1) {
                float2 r1 = *(const float2*)(res + (size_t)r0 * N + c0);
                float2 r2 = *(const float2*)(res + (size_t)(r0 + 8) * N + c0);
                v00 += r1.x; v01 += r1.y; v10 += r2.x; v11 += r2.y;
            }
            if (MODE == 2) {
                v00 = to_tf32(gelu_f(v00)); v01 = to_tf32(gelu_f(v01));
                v10 = to_tf32(gelu_f(v10)); v11 = to_tf32(gelu_f(v11));
            }
            *(float2*)(out + (size_t)r0 * N + c0) = make_float2(v00, v01);
            *(float2*)(out + (size_t)(r0 + 8) * N + c0) = make_float2(v10, v11);
        }
    }
}

// ------------------------------------------------------------------
// Attention: one block (128 threads) per (b, h, q). Output tf32-rounded
// (it only feeds the projection GEMM).
// ------------------------------------------------------------------
__global__ __launch_bounds__(128) void attn_kernel(const float* __restrict__ qkv,
                                                   float* __restrict__ y) {
    int t = blockIdx.x, h = blockIdx.y, b = blockIdx.z;
    int n = b * Tc + t;
    int tid = threadIdx.x;
    int lane = tid & 31, w = tid >> 5;

    __shared__ float sq[32];
    __shared__ float sc[Tc];
    __shared__ float red[8];
    __shared__ float accs[4][32];

    if (tid < 32) sq[tid] = qkv[(size_t)n * 3 * Cc + h * Dh + tid];
    __syncthreads();

    int nk = t + 1;
    const float scale = 0.17677669529663687f;  // 1/sqrt(32)

    for (int k = w; k < nk; k += 4) {
        const float* krow = qkv + (size_t)(b * Tc + k) * 3 * Cc + Cc + h * Dh;
        float p = sq[lane] * krow[lane];
#pragma unroll
        for (int o = 16; o; o >>= 1) p += __shfl_xor_sync(0xffffffffu, p, o);
        if (lane == 0) sc[k] = p * scale;
    }
    __syncthreads();

    float m = -INFINITY;
    for (int k = tid; k < nk; k += 128) m = fmaxf(m, sc[k]);
#pragma unroll
    for (int o = 16; o; o >>= 1) m = fmaxf(m, __shfl_xor_sync(0xffffffffu, m, o));
    if (lane == 0) red[w] = m;
    __syncthreads();
    m = fmaxf(fmaxf(red[0], red[1]), fmaxf(red[2], red[3]));
    __syncthreads();

    float s = 0.f;
    for (int k = tid; k < nk; k += 128) {
        float e = __expf(sc[k] - m);
        sc[k] = e;
        s += e;
    }
#pragma unroll
    for (int o = 16; o; o >>= 1) s += __shfl_xor_sync(0xffffffffu, s, o);
    if (lane == 0) red[4 + w] = s;
    __syncthreads();
    float inv = 1.0f / (red[4] + red[5] + red[6] + red[7]);

    float acc = 0.f;
    for (int k = w; k < nk; k += 4) {
        const float* vrow = qkv + (size_t)(b * Tc + k) * 3 * Cc + 2 * Cc + h * Dh;
        acc += sc[k] * vrow[lane];
    }
    accs[w][lane] = acc;
    __syncthreads();
    if (w == 0) {
        float o = (accs[0][lane] + accs[1][lane] + accs[2][lane] + accs[3][lane]) * inv;
        y[(size_t)n * Cc + h * Dh + lane] = to_tf32(o);
    }
}

// ------------------------------------------------------------------
// Host orchestration
// ------------------------------------------------------------------
extern "C" void kernel_launch(void* const* d_in, const int* in_sizes, int n_in,
                              void* d_out, int out_size) {
    const int*   idx    = (const int*)d_in[0];
    const float* tok    = (const float*)d_in[1];
    const float* pos    = (const float*)d_in[2];
    const float* ln1_g  = (const float*)d_in[3];
    const float* ln1_b  = (const float*)d_in[4];
    const float* wqkv   = (const float*)d_in[5];
    const float* bqkv   = (const float*)d_in[6];
    const float* wo     = (const float*)d_in[7];
    const float* bo     = (const float*)d_in[8];
    const float* ln2_g  = (const float*)d_in[9];
    const float* ln2_b  = (const float*)d_in[10];
    const float* wfc    = (const float*)d_in[11];
    const float* bfc    = (const float*)d_in[12];
    const float* wpr    = (const float*)d_in[13];
    const float* bpr    = (const float*)d_in[14];
    const float* lnf_g  = (const float*)d_in[15];
    const float* lnf_b  = (const float*)d_in[16];
    const float* w_lm   = (const float*)d_in[17];
    float* out = (float*)d_out;

    float *px, *pln, *pqkv, *pff, *pw;
    cudaGetSymbolAddress((void**)&px, g_x);
    cudaGetSymbolAddress((void**)&pln, g_ln);
    cudaGetSymbolAddress((void**)&pqkv, g_qkv);
    cudaGetSymbolAddress((void**)&pff, g_ff);
    cudaGetSymbolAddress((void**)&pw, g_w);

    float* cw_qkv = pw + W_QKV_OFF;
    float* cw_o   = pw + W_O_OFF;
    float* cw_fc  = pw + W_FC_OFF;
    float* cw_pr  = pw + W_PR_OFF;
    float* cw_lm  = pw + W_LM_OFF;

    // tf32-round all weights (off the hot GEMM path)
    cvt_kernel<<<512, 256>>>(wqkv, cw_qkv, Lc * Cc * 3 * Cc);
    cvt_kernel<<<512, 256>>>(wo,   cw_o,   Lc * Cc * Cc);
    cvt_kernel<<<512, 256>>>(wfc,  cw_fc,  Lc * Cc * FFc);
    cvt_kernel<<<512, 256>>>(wpr,  cw_pr,  Lc * FFc * Cc);
    cvt_kernel<<<128, 256>>>(w_lm, cw_lm,  Cc * Vc);

    // embedding
    embed_kernel<<<NTOK, Cc>>>(idx, tok, pos, px);

    for (int l = 0; l < Lc; l++) {
        const float* Wq = cw_qkv + (size_t)l * Cc * 3 * Cc;
        const float* bq = bqkv + (size_t)l * 3 * Cc;
        const float* Wo = cw_o + (size_t)l * Cc * Cc;
        const float* bo_ = bo + (size_t)l * Cc;
        const float* Wf = cw_fc + (size_t)l * Cc * FFc;
        const float* bf = bfc + (size_t)l * FFc;
        const float* Wp = cw_pr + (size_t)l * FFc * Cc;
        const float* bp = bpr + (size_t)l * Cc;

        // ln1
        ln_kernel<<<NTOK, Cc>>>(px, ln1_g + (size_t)l * Cc, ln1_b + (size_t)l * Cc, pln);
        // qkv = ln @ Wq + bq   [32768, 768]
        {
            dim3 grid((3 * Cc) / BN, NTOK / BM);
            gemm_tc<0><<<grid, 256>>>(pln, Wq, bq, nullptr, pqkv, NTOK, 3 * Cc, Cc);
        }
        // attention -> y into pln
        {
            dim3 grid(Tc, Hc, Bc);
            attn_kernel<<<grid, 128>>>(pqkv, pln);
        }
        // x = x + y @ Wo + bo
        {
            dim3 grid(Cc / BN, NTOK / BM);
            gemm_tc<1><<<grid, 256>>>(pln, Wo, bo_, px, px, NTOK, Cc, Cc);
        }
        // ln2
        ln_kernel<<<NTOK, Cc>>>(px, ln2_g + (size_t)l * Cc, ln2_b + (size_t)l * Cc, pln);
        // ff = gelu(ln @ Wf + bf)   [32768, 1024]
        {
            dim3 grid(FFc / BN, NTOK / BM);
            gemm_tc<2><<<grid, 256>>>(pln, Wf, bf, nullptr, pff, NTOK, FFc, Cc);
        }
        // x = x + ff @ Wp + bp
        {
            dim3 grid(Cc / BN, NTOK / BM);
            gemm_tc<1><<<grid, 256>>>(pff, Wp, bp, px, px, NTOK, Cc, FFc);
        }
    }

    // final ln
    ln_kernel<<<NTOK, Cc>>>(px, lnf_g, lnf_b, pln);
    // logits = ln @ w_lm   [32768, 128], no bias
    {
        dim3 grid(Vc / BN, NTOK / BM);
        gemm_tc<0><<<grid, 256>>>(pln, cw_lm, nullptr, nullptr, out, NTOK, Vc, Cc);
    }
}

// round 4
// speedup vs baseline: 4.2222x; 3.6826x over previous
#include <cuda_runtime.h>
#include <cuda_bf16.h>
#include <math.h>
#include <stdint.h>

// ---- problem constants (gpt-small) ----
#define Lc 8
#define Hc 8
#define Cc 256
#define Vc 128
#define Tc 1024
#define Bc 32
#define Dh 32
#define FFc 1024
#define NTOK (Bc * Tc)   // 32768

// ---- scratch (device globals; no allocation allowed) ----
__device__ float g_x[(size_t)NTOK * Cc];     // residual stream
__device__ float g_ln[(size_t)NTOK * Cc];    // LN output / attention y (tf32-rounded)
__device__ float g_qkv[(size_t)NTOK * 3 * Cc];
__device__ float g_ff[(size_t)NTOK * FFc];   // fc (gelu) output (tf32-rounded)

// tf32-rounded weights: qkv | wo | wfc | wpr | w_lm
#define W_QKV_OFF 0
#define W_O_OFF   (W_QKV_OFF + (size_t)Lc * Cc * 3 * Cc)
#define W_FC_OFF  (W_O_OFF   + (size_t)Lc * Cc * Cc)
#define W_PR_OFF  (W_FC_OFF  + (size_t)Lc * Cc * FFc)
#define W_LM_OFF  (W_PR_OFF  + (size_t)Lc * FFc * Cc)
#define W_TOTAL   (W_LM_OFF  + (size_t)Cc * Vc)
__device__ float g_w[W_TOTAL];

// ------------------------------------------------------------------
// helpers
// ------------------------------------------------------------------
__device__ __forceinline__ float to_tf32(float x) {
    uint32_t u;
    asm("cvt.rna.tf32.f32 %0, %1;" : "=r"(u) : "f"(x));
    return __uint_as_float(u);
}

__device__ __forceinline__ float gelu_f(float x) {
    float x3 = x * x * x;
    return 0.5f * x * (1.0f + tanhf(0.7978845608028654f * (x + 0.044715f * x3)));
}

__device__ __forceinline__ uint32_t smem_u32(const void* p) {
    uint32_t a;
    asm("{.reg .u64 t; cvta.to.shared.u64 t, %1; cvt.u32.u64 %0, t;}" : "=r"(a) : "l"(p));
    return a;
}

__device__ __forceinline__ void cp16(uint32_t dst, const void* src) {
    asm volatile("cp.async.cg.shared.global [%0], [%1], 16;\n" :: "r"(dst), "l"(src));
}

__device__ __forceinline__ void mma_tf32(float* c, const uint32_t* a, const uint32_t* b) {
    asm volatile(
        "mma.sync.aligned.m16n8k8.row.col.f32.tf32.tf32.f32 "
        "{%0,%1,%2,%3}, {%4,%5,%6,%7}, {%8,%9}, {%0,%1,%2,%3};\n"
        : "+f"(c[0]), "+f"(c[1]), "+f"(c[2]), "+f"(c[3])
        : "r"(a[0]), "r"(a[1]), "r"(a[2]), "r"(a[3]), "r"(b[0]), "r"(b[1]));
}

// ------------------------------------------------------------------
// weight tf32-rounding (once per call, off the hot path)
// ------------------------------------------------------------------
__global__ void cvt_kernel(const float* __restrict__ in, float* __restrict__ out, int n) {
    for (int i = blockIdx.x * blockDim.x + threadIdx.x; i < n; i += gridDim.x * blockDim.x)
        out[i] = to_tf32(in[i]);
}

// ------------------------------------------------------------------
// Embedding
// ------------------------------------------------------------------
__global__ void embed_kernel(const int* __restrict__ idx,
                             const float* __restrict__ tok,
                             const float* __restrict__ pos,
                             float* __restrict__ x) {
    int n = blockIdx.x;
    int c = threadIdx.x;
    int token = idx[n];
    x[(size_t)n * Cc + c] = tok[(size_t)token * Cc + c] + pos[(size_t)(n % Tc) * Cc + c];
}

// ------------------------------------------------------------------
// LayerNorm (output tf32-rounded: it only ever feeds GEMM-A)
// ------------------------------------------------------------------
__global__ void ln_kernel(const float* __restrict__ x,
                          const float* __restrict__ g,
                          const float* __restrict__ b,
                          float* __restrict__ out) {
    int row = blockIdx.x;
    int tid = threadIdx.x;
    int w = tid >> 5, lane = tid & 31;
    float v = x[(size_t)row * Cc + tid];

    __shared__ float sm[8];
    __shared__ float sm2[8];

    float s = v;
#pragma unroll
    for (int o = 16; o; o >>= 1) s += __shfl_xor_sync(0xffffffffu, s, o);
    if (lane == 0) sm[w] = s;
    __syncthreads();
    float tot = 0.f;
#pragma unroll
    for (int i = 0; i < 8; i++) tot += sm[i];
    float mean = tot * (1.0f / Cc);

    float d = v - mean;
    float q = d * d;
#pragma unroll
    for (int o = 16; o; o >>= 1) q += __shfl_xor_sync(0xffffffffu, q, o);
    if (lane == 0) sm2[w] = q;
    __syncthreads();
    float vtot = 0.f;
#pragma unroll
    for (int i = 0; i < 8; i++) vtot += sm2[i];
    float var = vtot * (1.0f / Cc);

    out[(size_t)row * Cc + tid] = to_tf32(d * rsqrtf(var + 1e-5f) * g[tid] + b[tid]);
}

// ------------------------------------------------------------------
// Tensor-core GEMM (unchanged from R2)
// ------------------------------------------------------------------
#define BM 128
#define BN 128
#define BK 16
#define ASTRIDE 20
#define BSTRIDE 136

template <int MODE>
__global__ __launch_bounds__(256) void gemm_tc(
    const float* __restrict__ A, const float* __restrict__ B,
    const float* __restrict__ bias, const float* __restrict__ res,
    float* __restrict__ out, int M, int N, int K) {
    __shared__ float As[2][BM * ASTRIDE];
    __shared__ float Bs[2][BK * BSTRIDE];

    int tid = threadIdx.x;
    int bm = blockIdx.y * BM;
    int bn = blockIdx.x * BN;
    int lane = tid & 31, wid = tid >> 5;
    int wm = (wid >> 2) * 64;
    int wn = (wid & 3) * 32;
    int grp = lane >> 2, tig = lane & 3;

    float acc[4][4][4];
#pragma unroll
    for (int i = 0; i < 4; i++)
#pragma unroll
        for (int j = 0; j < 4; j++)
#pragma unroll
            for (int k = 0; k < 4; k++) acc[i][j][k] = 0.f;

    uint32_t sA0 = smem_u32(As[0]), sA1 = smem_u32(As[1]);
    uint32_t sB0 = smem_u32(Bs[0]), sB1 = smem_u32(Bs[1]);

    int am = tid >> 2;
    int ak = (tid & 3) << 2;
    int br = tid >> 5;
    int bnv = (tid & 31) << 2;

    const float* gA0 = A + (size_t)(bm + am) * K + ak;
    const float* gA1 = A + (size_t)(bm + am + 64) * K + ak;
    const float* gB0 = B + (size_t)br * N + bn + bnv;
    const float* gB1 = B + (size_t)(br + 8) * N + bn + bnv;

    uint32_t dA0 = (uint32_t)((am * ASTRIDE + ak) * 4);
    uint32_t dA1 = (uint32_t)(((am + 64) * ASTRIDE + ak) * 4);
    uint32_t dB0 = (uint32_t)((br * BSTRIDE + bnv) * 4);
    uint32_t dB1 = (uint32_t)(((br + 8) * BSTRIDE + bnv) * 4);

    int KT = K / BK;

    {
        cp16(sA0 + dA0, gA0);
        cp16(sA0 + dA1, gA1);
        cp16(sB0 + dB0, gB0);
        cp16(sB0 + dB1, gB1);
        asm volatile("cp.async.commit_group;\n" ::: "memory");
    }

    int buf = 0;
    for (int kt = 0; kt < KT; kt++) {
        asm volatile("cp.async.wait_group 0;\n" ::: "memory");
        __syncthreads();

        if (kt + 1 < KT) {
            uint32_t a_s = buf ? sA0 : sA1;
            uint32_t b_s = buf ? sB0 : sB1;
            int ko = (kt + 1) * BK;
            cp16(a_s + dA0, gA0 + ko);
            cp16(a_s + dA1, gA1 + ko);
            cp16(b_s + dB0, gB0 + (size_t)ko * N);
            cp16(b_s + dB1, gB1 + (size_t)ko * N);
            asm volatile("cp.async.commit_group;\n" ::: "memory");
        }

        const float* as = As[buf];
        const float* bs = Bs[buf];
#pragma unroll
        for (int kk = 0; kk < 2; kk++) {
            int k0 = kk * 8;
            uint32_t a[4][4], b[4][2];
#pragma unroll
            for (int mi = 0; mi < 4; mi++) {
                int r = wm + mi * 16 + grp;
                a[mi][0] = __float_as_uint(as[r * ASTRIDE + k0 + tig]);
                a[mi][1] = __float_as_uint(as[(r + 8) * ASTRIDE + k0 + tig]);
                a[mi][2] = __float_as_uint(as[r * ASTRIDE + k0 + tig + 4]);
                a[mi][3] = __float_as_uint(as[(r + 8) * ASTRIDE + k0 + tig + 4]);
            }
#pragma unroll
            for (int ni = 0; ni < 4; ni++) {
                int c = wn + ni * 8 + grp;
                b[ni][0] = __float_as_uint(bs[(k0 + tig) * BSTRIDE + c]);
                b[ni][1] = __float_as_uint(bs[(k0 + tig + 4) * BSTRIDE + c]);
            }
#pragma unroll
            for (int mi = 0; mi < 4; mi++)
#pragma unroll
                for (int ni = 0; ni < 4; ni++)
                    mma_tf32(acc[mi][ni], a[mi], b[ni]);
        }
        buf ^= 1;
    }

#pragma unroll
    for (int mi = 0; mi < 4; mi++) {
        int r0 = bm + wm + mi * 16 + grp;
#pragma unroll
        for (int ni = 0; ni < 4; ni++) {
            int c0 = bn + wn + ni * 8 + 2 * tig;
            float v00 = acc[mi][ni][0], v01 = acc[mi][ni][1];
            float v10 = acc[mi][ni][2], v11 = acc[mi][ni][3];
            if (bias) {
                float b0 = bias[c0], b1 = bias[c0 + 1];
                v00 += b0; v01 += b1; v10 += b0; v11 += b1;
            }
            if (MODE == 1) {
                float2 r1 = *(const float2*)(res + (size_t)r0 * N + c0);
                float2 r2 = *(const float2*)(res + (size_t)(r0 + 8) * N + c0);
                v00 += r1.x; v01 += r1.y; v10 += r2.x; v11 += r2.y;
            }
            if (MODE == 2) {
                v00 = to_tf32(gelu_f(v00)); v01 = to_tf32(gelu_f(v01));
                v10 = to_tf32(gelu_f(v10)); v11 = to_tf32(gelu_f(v11));
            }
            *(float2*)(out + (size_t)r0 * N + c0) = make_float2(v00, v01);
            *(float2*)(out + (size_t)(r0 + 8) * N + c0) = make_float2(v10, v11);
        }
    }
}

// ------------------------------------------------------------------
// Flash attention (SIMT, fp32): one block = 256 queries of one (b,h),
// one thread = one query (q and o register-resident), online softmax.
// K/V tiles of 64 keys in shared memory; smem reads are broadcast.
// ------------------------------------------------------------------
#define ATQ 256
#define ATK 64

__global__ __launch_bounds__(256) void attn_flash(const float* __restrict__ qkv,
                                                  float* __restrict__ y) {
    int qi = blockIdx.x, h = blockIdx.y, b = blockIdx.z;
    int qbase = qi * ATQ;
    int tid = threadIdx.x;
    int q = qbase + tid;
    size_t rowbase = (size_t)b * Tc;

    __shared__ float Ks[ATK][32];
    __shared__ float Vs[ATK][32];

    // load this thread's query into registers
    float4 qreg[8];
    const float4* qp = (const float4*)(qkv + (rowbase + q) * (3 * Cc) + h * Dh);
#pragma unroll
    for (int j = 0; j < 8; j++) qreg[j] = qp[j];

    float o[32];
#pragma unroll
    for (int d = 0; d < 32; d++) o[d] = 0.f;
    float m = -INFINITY, l = 0.f;

    const float scale = 0.17677669529663687f;  // 1/sqrt(32)
    int nkt = (qbase + ATQ) / ATK;              // key tiles this block needs

    for (int kt = 0; kt < nkt; kt++) {
        int kbase = kt * ATK;
        bool masked = (kbase >= qbase);

        __syncthreads();
        // cooperative K/V tile load: 64 rows x 32 floats each
#pragma unroll
        for (int j = 0; j < 2; j++) {
            int i = tid + j * 256;
            int r = i >> 3, c = i & 7;
            const float* krow = qkv + (rowbase + kbase + r) * (3 * Cc) + Cc + h * Dh;
            const float* vrow = qkv + (rowbase + kbase + r) * (3 * Cc) + 2 * Cc + h * Dh;
            ((float4*)Ks[r])[c] = ((const float4*)krow)[c];
            ((float4*)Vs[r])[c] = ((const float4*)vrow)[c];
        }
        __syncthreads();

#pragma unroll 1
        for (int c0 = 0; c0 < ATK; c0 += 16) {
            float s[16];
#pragma unroll
            for (int kk = 0; kk < 16; kk++) {
                const float4* kr = (const float4*)Ks[c0 + kk];
                float acc = 0.f;
#pragma unroll
                for (int j = 0; j < 8; j++) {
                    float4 kv = kr[j];
                    acc += qreg[j].x * kv.x + qreg[j].y * kv.y
                         + qreg[j].z * kv.z + qreg[j].w * kv.w;
                }
                int key = kbase + c0 + kk;
                s[kk] = (!masked || key <= q) ? acc * scale : -INFINITY;
            }

            float cm = s[0];
#pragma unroll
            for (int kk = 1; kk < 16; kk++) cm = fmaxf(cm, s[kk]);

            if (cm > m) {
                float alpha = __expf(m - cm);   // exp(-inf)=0 on first update
                l *= alpha;
#pragma unroll
                for (int d = 0; d < 32; d++) o[d] *= alpha;
                m = cm;
            }

#pragma unroll
            for (int kk = 0; kk < 16; kk++) {
                float p = __expf(s[kk] - m);    // masked -> exp(-inf)=0
                l += p;
                const float4* vr = (const float4*)Vs[c0 + kk];
#pragma unroll
                for (int j = 0; j < 8; j++) {
                    float4 vv = vr[j];
                    o[4 * j + 0] += p * vv.x;
                    o[4 * j + 1] += p * vv.y;
                    o[4 * j + 2] += p * vv.z;
                    o[4 * j + 3] += p * vv.w;
                }
            }
        }
    }

    float inv = 1.0f / l;
    float4* yp = (float4*)(y + (rowbase + q) * Cc + h * Dh);
#pragma unroll
    for (int j = 0; j < 8; j++) {
        float4 w;
        w.x = to_tf32(o[4 * j + 0] * inv);
        w.y = to_tf32(o[4 * j + 1] * inv);
        w.z = to_tf32(o[4 * j + 2] * inv);
        w.w = to_tf32(o[4 * j + 3] * inv);
        yp[j] = w;
    }
}

// ------------------------------------------------------------------
// Host orchestration
// ------------------------------------------------------------------
extern "C" void kernel_launch(void* const* d_in, const int* in_sizes, int n_in,
                              void* d_out, int out_size) {
    const int*   idx    = (const int*)d_in[0];
    const float* tok    = (const float*)d_in[1];
    const float* pos    = (const float*)d_in[2];
    const float* ln1_g  = (const float*)d_in[3];
    const float* ln1_b  = (const float*)d_in[4];
    const float* wqkv   = (const float*)d_in[5];
    const float* bqkv   = (const float*)d_in[6];
    const float* wo     = (const float*)d_in[7];
    const float* bo     = (const float*)d_in[8];
    const float* ln2_g  = (const float*)d_in[9];
    const float* ln2_b  = (const float*)d_in[10];
    const float* wfc    = (const float*)d_in[11];
    const float* bfc    = (const float*)d_in[12];
    const float* wpr    = (const float*)d_in[13];
    const float* bpr    = (const float*)d_in[14];
    const float* lnf_g  = (const float*)d_in[15];
    const float* lnf_b  = (const float*)d_in[16];
    const float* w_lm   = (const float*)d_in[17];
    float* out = (float*)d_out;

    float *px, *pln, *pqkv, *pff, *pw;
    cudaGetSymbolAddress((void**)&px, g_x);
    cudaGetSymbolAddress((void**)&pln, g_ln);
    cudaGetSymbolAddress((void**)&pqkv, g_qkv);
    cudaGetSymbolAddress((void**)&pff, g_ff);
    cudaGetSymbolAddress((void**)&pw, g_w);

    float* cw_qkv = pw + W_QKV_OFF;
    float* cw_o   = pw + W_O_OFF;
    float* cw_fc  = pw + W_FC_OFF;
    float* cw_pr  = pw + W_PR_OFF;
    float* cw_lm  = pw + W_LM_OFF;

    cvt_kernel<<<512, 256>>>(wqkv, cw_qkv, Lc * Cc * 3 * Cc);
    cvt_kernel<<<512, 256>>>(wo,   cw_o,   Lc * Cc * Cc);
    cvt_kernel<<<512, 256>>>(wfc,  cw_fc,  Lc * Cc * FFc);
    cvt_kernel<<<512, 256>>>(wpr,  cw_pr,  Lc * FFc * Cc);
    cvt_kernel<<<128, 256>>>(w_lm, cw_lm,  Cc * Vc);

    embed_kernel<<<NTOK, Cc>>>(idx, tok, pos, px);

    for (int l = 0; l < Lc; l++) {
        const float* Wq = cw_qkv + (size_t)l * Cc * 3 * Cc;
        const float* bq = bqkv + (size_t)l * 3 * Cc;
        const float* Wo = cw_o + (size_t)l * Cc * Cc;
        const float* bo_ = bo + (size_t)l * Cc;
        const float* Wf = cw_fc + (size_t)l * Cc * FFc;
        const float* bf = bfc + (size_t)l * FFc;
        const float* Wp = cw_pr + (size_t)l * FFc * Cc;
        const float* bp = bpr + (size_t)l * Cc;

        ln_kernel<<<NTOK, Cc>>>(px, ln1_g + (size_t)l * Cc, ln1_b + (size_t)l * Cc, pln);
        {
            dim3 grid((3 * Cc) / BN, NTOK / BM);
            gemm_tc<0><<<grid, 256>>>(pln, Wq, bq, nullptr, pqkv, NTOK, 3 * Cc, Cc);
        }
        {
            dim3 grid(Tc / ATQ, Hc, Bc);
            attn_flash<<<grid, 256>>>(pqkv, pln);
        }
        {
            dim3 grid(Cc / BN, NTOK / BM);
            gemm_tc<1><<<grid, 256>>>(pln, Wo, bo_, px, px, NTOK, Cc, Cc);
        }
        ln_kernel<<<NTOK, Cc>>>(px, ln2_g + (size_t)l * Cc, ln2_b + (size_t)l * Cc, pln);
        {
            dim3 grid(FFc / BN, NTOK / BM);
            gemm_tc<2><<<grid, 256>>>(pln, Wf, bf, nullptr, pff, NTOK, FFc, Cc);
        }
        {
            dim3 grid(Cc / BN, NTOK / BM);
            gemm_tc<1><<<grid, 256>>>(pff, Wp, bp, px, px, NTOK, Cc, FFc);
        }
    }

    ln_kernel<<<NTOK, Cc>>>(px, lnf_g, lnf_b, pln);
    {
        dim3 grid(Vc / BN, NTOK / BM);
        gemm_tc<0><<<grid, 256>>>(pln, cw_lm, nullptr, nullptr, out, NTOK, Vc, Cc);
    }
}

// round 7
// speedup vs baseline: 4.2930x; 1.0168x over previous
#include <cuda_runtime.h>
#include <cuda_bf16.h>
#include <math.h>
#include <stdint.h>

// ---- problem constants (gpt-small) ----
#define Lc 8
#define Hc 8
#define Cc 256
#define Vc 128
#define Tc 1024
#define Bc 32
#define Dh 32
#define FFc 1024
#define NTOK (Bc * Tc)   // 32768

// ---- scratch (device globals; no allocation allowed) ----
__device__ float g_x[(size_t)NTOK * Cc];     // residual stream
__device__ float g_ln[(size_t)NTOK * Cc];    // LN output / attention y (tf32-rounded)
__device__ float g_qkv[(size_t)NTOK * 3 * Cc];
__device__ float g_ff[(size_t)NTOK * FFc];   // fc (gelu) output (tf32-rounded)

// tf32-rounded weights: qkv | wo | wfc | wpr | w_lm  (natural [K,N] layout)
#define W_QKV_OFF 0
#define W_O_OFF   (W_QKV_OFF + (size_t)Lc * Cc * 3 * Cc)
#define W_FC_OFF  (W_O_OFF   + (size_t)Lc * Cc * Cc)
#define W_PR_OFF  (W_FC_OFF  + (size_t)Lc * Cc * FFc)
#define W_LM_OFF  (W_PR_OFF  + (size_t)Lc * FFc * Cc)
#define W_TOTAL   (W_LM_OFF  + (size_t)Cc * Vc)
__device__ float g_w[W_TOTAL];

// ------------------------------------------------------------------
// helpers
// ------------------------------------------------------------------
__device__ __forceinline__ float to_tf32(float x) {
    uint32_t u;
    asm("cvt.rna.tf32.f32 %0, %1;" : "=r"(u) : "f"(x));
    return __uint_as_float(u);
}

__device__ __forceinline__ float gelu_f(float x) {
    float x3 = x * x * x;
    return 0.5f * x * (1.0f + tanhf(0.7978845608028654f * (x + 0.044715f * x3)));
}

__device__ __forceinline__ uint32_t smem_u32(const void* p) {
    uint32_t a;
    asm("{.reg .u64 t; cvta.to.shared.u64 t, %1; cvt.u32.u64 %0, t;}" : "=r"(a) : "l"(p));
    return a;
}

__device__ __forceinline__ void cp16(uint32_t dst, const void* src) {
    asm volatile("cp.async.cg.shared.global [%0], [%1], 16;\n" :: "r"(dst), "l"(src));
}

__device__ __forceinline__ void mma_tf32(float* c, const uint32_t* a, const uint32_t* b) {
    asm volatile(
        "mma.sync.aligned.m16n8k8.row.col.f32.tf32.tf32.f32 "
        "{%0,%1,%2,%3}, {%4,%5,%6,%7}, {%8,%9}, {%0,%1,%2,%3};\n"
        : "+f"(c[0]), "+f"(c[1]), "+f"(c[2]), "+f"(c[3])
        : "r"(a[0]), "r"(a[1]), "r"(a[2]), "r"(a[3]), "r"(b[0]), "r"(b[1]));
}

// ------------------------------------------------------------------
// weight tf32-rounding (once per call, off the hot path)
// ------------------------------------------------------------------
__global__ void cvt_kernel(const float* __restrict__ in, float* __restrict__ out, int n) {
    for (int i = blockIdx.x * blockDim.x + threadIdx.x; i < n; i += gridDim.x * blockDim.x)
        out[i] = to_tf32(in[i]);
}

// ------------------------------------------------------------------
// Embedding
// ------------------------------------------------------------------
__global__ void embed_kernel(const int* __restrict__ idx,
                             const float* __restrict__ tok,
                             const float* __restrict__ pos,
                             float* __restrict__ x) {
    int n = blockIdx.x;
    int c = threadIdx.x;
    int token = idx[n];
    x[(size_t)n * Cc + c] = tok[(size_t)token * Cc + c] + pos[(size_t)(n % Tc) * Cc + c];
}

// ------------------------------------------------------------------
// LayerNorm (output tf32-rounded: it only ever feeds GEMM-A)
// ------------------------------------------------------------------
__global__ void ln_kernel(const float* __restrict__ x,
                          const float* __restrict__ g,
                          const float* __restrict__ b,
                          float* __restrict__ out) {
    int row = blockIdx.x;
    int tid = threadIdx.x;
    int w = tid >> 5, lane = tid & 31;
    float v = x[(size_t)row * Cc + tid];

    __shared__ float sm[8];
    __shared__ float sm2[8];

    float s = v;
#pragma unroll
    for (int o = 16; o; o >>= 1) s += __shfl_xor_sync(0xffffffffu, s, o);
    if (lane == 0) sm[w] = s;
    __syncthreads();
    float tot = 0.f;
#pragma unroll
    for (int i = 0; i < 8; i++) tot += sm[i];
    float mean = tot * (1.0f / Cc);

    float d = v - mean;
    float q = d * d;
#pragma unroll
    for (int o = 16; o; o >>= 1) q += __shfl_xor_sync(0xffffffffu, q, o);
    if (lane == 0) sm2[w] = q;
    __syncthreads();
    float vtot = 0.f;
#pragma unroll
    for (int i = 0; i < 8; i++) vtot += sm2[i];
    float var = vtot * (1.0f / Cc);

    out[(size_t)row * Cc + tid] = to_tf32(d * rsqrtf(var + 1e-5f) * g[tid] + b[tid]);
}

// ------------------------------------------------------------------
// Tensor-core GEMM (mma.sync tf32): out = A[M,K] @ B[K,N] (+bias)(+res)(+gelu)
// BM=128 BN=128 BK=32, 256 threads (8 warps, 64x32 warp tile),
// 2-stage cp.async pipeline in dynamic smem, 2 CTAs/SM.
// MODE: 0=bias, 1=bias+residual, 2=bias+gelu(->tf32)
// ------------------------------------------------------------------
#define BM 128
#define BN 128
#define BK 32
#define ASTRIDE 36     // BK + 4 pad
#define BSTRIDE 136    // BN + 8 pad
#define ABYTES (BM * ASTRIDE * 4)   // 18432
#define BBYTES (BK * BSTRIDE * 4)   // 17408
#define SMEM_GEMM (2 * ABYTES + 2 * BBYTES)  // 71680

template <int MODE>
__global__ __launch_bounds__(256, 2) void gemm_tc(
    const float* __restrict__ A, const float* __restrict__ B,
    const float* __restrict__ bias, const float* __restrict__ res,
    float* __restrict__ out, int M, int N, int K) {
    extern __shared__ float smem[];
    float* Asm[2] = { smem, smem + BM * ASTRIDE };
    float* Bsm[2] = { smem + 2 * BM * ASTRIDE, smem + 2 * BM * ASTRIDE + BK * BSTRIDE };

    int tid = threadIdx.x;
    int bm = blockIdx.y * BM;
    int bn = blockIdx.x * BN;
    int lane = tid & 31, wid = tid >> 5;
    int wm = (wid >> 2) * 64;   // warp M offset (0/64)
    int wn = (wid & 3) * 32;    // warp N offset (0/32/64/96)
    int grp = lane >> 2, tig = lane & 3;

    float acc[4][4][4];
#pragma unroll
    for (int i = 0; i < 4; i++)
#pragma unroll
        for (int j = 0; j < 4; j++)
#pragma unroll
            for (int k = 0; k < 4; k++) acc[i][j][k] = 0.f;

    uint32_t sA[2] = { smem_u32(Asm[0]), smem_u32(Asm[1]) };
    uint32_t sB[2] = { smem_u32(Bsm[0]), smem_u32(Bsm[1]) };

    int KT = K / BK;

    // copy one BK-stage into buffer buf: A 128x32, B 32x128 (8 cp16/thread)
    auto copy_stage = [&](int s, int buf) {
        int k0 = s * BK;
#pragma unroll
        for (int i = 0; i < 4; i++) {
            int id = tid + i * 256;        // 0..1023
            int row = id >> 3;             // 0..127
            int kk = (id & 7) << 2;        // 0,4,...,28
            cp16(sA[buf] + (uint32_t)((row * ASTRIDE + kk) * 4),
                 A + (size_t)(bm + row) * K + k0 + kk);
        }
#pragma unroll
        for (int i = 0; i < 4; i++) {
            int id = tid + i * 256;        // 0..1023
            int krow = id >> 5;            // 0..31
            int nn = (id & 31) << 2;       // 0,4,...,124
            cp16(sB[buf] + (uint32_t)((krow * BSTRIDE + nn) * 4),
                 B + (size_t)(k0 + krow) * N + bn + nn);
        }
        asm volatile("cp.async.commit_group;\n" ::: "memory");
    };

    copy_stage(0, 0);

    for (int s = 0; s < KT; s++) {
        int buf = s & 1;
        asm volatile("cp.async.wait_group 0;\n" ::: "memory");
        __syncthreads();

        if (s + 1 < KT) copy_stage(s + 1, buf ^ 1);

        const float* as = Asm[buf];
        const float* bs = Bsm[buf];
#pragma unroll
        for (int kk = 0; kk < 4; kk++) {
            int k0 = kk * 8;
            uint32_t a[4][4], b[4][2];
#pragma unroll
            for (int mi = 0; mi < 4; mi++) {
                int r = wm + mi * 16 + grp;
                a[mi][0] = __float_as_uint(as[r * ASTRIDE + k0 + tig]);
                a[mi][1] = __float_as_uint(as[(r + 8) * ASTRIDE + k0 + tig]);
                a[mi][2] = __float_as_uint(as[r * ASTRIDE + k0 + tig + 4]);
                a[mi][3] = __float_as_uint(as[(r + 8) * ASTRIDE + k0 + tig + 4]);
            }
#pragma unroll
            for (int ni = 0; ni < 4; ni++) {
                int c = wn + ni * 8 + grp;
                b[ni][0] = __float_as_uint(bs[(k0 + tig) * BSTRIDE + c]);
                b[ni][1] = __float_as_uint(bs[(k0 + tig + 4) * BSTRIDE + c]);
            }
#pragma unroll
            for (int mi = 0; mi < 4; mi++)
#pragma unroll
                for (int ni = 0; ni < 4; ni++)
                    mma_tf32(acc[mi][ni], a[mi], b[ni]);
        }
        __syncthreads();
    }

    // epilogue
#pragma unroll
    for (int mi = 0; mi < 4; mi++) {
        int r0 = bm + wm + mi * 16 + grp;
#pragma unroll
        for (int ni = 0; ni < 4; ni++) {
            int c0 = bn + wn + ni * 8 + 2 * tig;
            float v00 = acc[mi][ni][0], v01 = acc[mi][ni][1];
            float v10 = acc[mi][ni][2], v11 = acc[mi][ni][3];
            if (bias) {
                float b0 = bias[c0], b1 = bias[c0 + 1];
                v00 += b0; v01 += b1; v10 += b0; v11 += b1;
            }
            if (MODE == 1) {
                float2 r1 = *(const float2*)(res + (size_t)r0 * N + c0);
                float2 r2 = *(const float2*)(res + (size_t)(r0 + 8) * N + c0);
                v00 += r1.x; v01 += r1.y; v10 += r2.x; v11 += r2.y;
            }
            if (MODE == 2) {
                v00 = to_tf32(gelu_f(v00)); v01 = to_tf32(gelu_f(v01));
                v10 = to_tf32(gelu_f(v10)); v11 = to_tf32(gelu_f(v11));
            }
            *(float2*)(out + (size_t)r0 * N + c0) = make_float2(v00, v01);
            *(float2*)(out + (size_t)(r0 + 8) * N + c0) = make_float2(v10, v11);
        }
    }
}

// ------------------------------------------------------------------
// Flash attention (SIMT, fp32) — unchanged from R3
// ------------------------------------------------------------------
#define ATQ 256
#define ATK 64

__global__ __launch_bounds__(256) void attn_flash(const float* __restrict__ qkv,
                                                  float* __restrict__ y) {
    int qi = blockIdx.x, h = blockIdx.y, b = blockIdx.z;
    int qbase = qi * ATQ;
    int tid = threadIdx.x;
    int q = qbase + tid;
    size_t rowbase = (size_t)b * Tc;

    __shared__ float Ks[ATK][32];
    __shared__ float Vs[ATK][32];

    float4 qreg[8];
    const float4* qp = (const float4*)(qkv + (rowbase + q) * (3 * Cc) + h * Dh);
#pragma unroll
    for (int j = 0; j < 8; j++) qreg[j] = qp[j];

    float o[32];
#pragma unroll
    for (int d = 0; d < 32; d++) o[d] = 0.f;
    float m = -INFINITY, l = 0.f;

    const float scale = 0.17677669529663687f;
    int nkt = (qbase + ATQ) / ATK;

    for (int kt = 0; kt < nkt; kt++) {
        int kbase = kt * ATK;
        bool masked = (kbase >= qbase);

        __syncthreads();
#pragma unroll
        for (int j = 0; j < 2; j++) {
            int i = tid + j * 256;
            int r = i >> 3, c = i & 7;
            const float* krow = qkv + (rowbase + kbase + r) * (3 * Cc) + Cc + h * Dh;
            const float* vrow = qkv + (rowbase + kbase + r) * (3 * Cc) + 2 * Cc + h * Dh;
            ((float4*)Ks[r])[c] = ((const float4*)krow)[c];
            ((float4*)Vs[r])[c] = ((const float4*)vrow)[c];
        }
        __syncthreads();

#pragma unroll 1
        for (int c0 = 0; c0 < ATK; c0 += 16) {
            float s[16];
#pragma unroll
            for (int kk = 0; kk < 16; kk++) {
                const float4* kr = (const float4*)Ks[c0 + kk];
                float acc = 0.f;
#pragma unroll
                for (int j = 0; j < 8; j++) {
                    float4 kv = kr[j];
                    acc += qreg[j].x * kv.x + qreg[j].y * kv.y
                         + qreg[j].z * kv.z + qreg[j].w * kv.w;
                }
                int key = kbase + c0 + kk;
                s[kk] = (!masked || key <= q) ? acc * scale : -INFINITY;
            }

            float cm = s[0];
#pragma unroll
            for (int kk = 1; kk < 16; kk++) cm = fmaxf(cm, s[kk]);

            if (cm > m) {
                float alpha = __expf(m - cm);
                l *= alpha;
#pragma unroll
                for (int d = 0; d < 32; d++) o[d] *= alpha;
                m = cm;
            }

#pragma unroll
            for (int kk = 0; kk < 16; kk++) {
                float p = __expf(s[kk] - m);
                l += p;
                const float4* vr = (const float4*)Vs[c0 + kk];
#pragma unroll
                for (int j = 0; j < 8; j++) {
                    float4 vv = vr[j];
                    o[4 * j + 0] += p * vv.x;
                    o[4 * j + 1] += p * vv.y;
                    o[4 * j + 2] += p * vv.z;
                    o[4 * j + 3] += p * vv.w;
                }
            }
        }
    }

    float inv = 1.0f / l;
    float4* yp = (float4*)(y + (rowbase + q) * Cc + h * Dh);
#pragma unroll
    for (int j = 0; j < 8; j++) {
        float4 w;
        w.x = to_tf32(o[4 * j + 0] * inv);
        w.y = to_tf32(o[4 * j + 1] * inv);
        w.z = to_tf32(o[4 * j + 2] * inv);
        w.w = to_tf32(o[4 * j + 3] * inv);
        yp[j] = w;
    }
}

// ------------------------------------------------------------------
// Host orchestration
// ------------------------------------------------------------------
extern "C" void kernel_launch(void* const* d_in, const int* in_sizes, int n_in,
                              void* d_out, int out_size) {
    const int*   idx    = (const int*)d_in[0];
    const float* tok    = (const float*)d_in[1];
    const float* pos    = (const float*)d_in[2];
    const float* ln1_g  = (const float*)d_in[3];
    const float* ln1_b  = (const float*)d_in[4];
    const float* wqkv   = (const float*)d_in[5];
    const float* bqkv   = (const float*)d_in[6];
    const float* wo     = (const float*)d_in[7];
    const float* bo     = (const float*)d_in[8];
    const float* ln2_g  = (const float*)d_in[9];
    const float* ln2_b  = (const float*)d_in[10];
    const float* wfc    = (const float*)d_in[11];
    const float* bfc    = (const float*)d_in[12];
    const float* wpr    = (const float*)d_in[13];
    const float* bpr    = (const float*)d_in[14];
    const float* lnf_g  = (const float*)d_in[15];
    const float* lnf_b  = (const float*)d_in[16];
    const float* w_lm   = (const float*)d_in[17];
    float* out = (float*)d_out;

    float *px, *pln, *pqkv, *pff, *pw;
    cudaGetSymbolAddress((void**)&px, g_x);
    cudaGetSymbolAddress((void**)&pln, g_ln);
    cudaGetSymbolAddress((void**)&pqkv, g_qkv);
    cudaGetSymbolAddress((void**)&pff, g_ff);
    cudaGetSymbolAddress((void**)&pw, g_w);

    float* cw_qkv = pw + W_QKV_OFF;
    float* cw_o   = pw + W_O_OFF;
    float* cw_fc  = pw + W_FC_OFF;
    float* cw_pr  = pw + W_PR_OFF;
    float* cw_lm  = pw + W_LM_OFF;

    cudaFuncSetAttribute(gemm_tc<0>, cudaFuncAttributeMaxDynamicSharedMemorySize, SMEM_GEMM);
    cudaFuncSetAttribute(gemm_tc<1>, cudaFuncAttributeMaxDynamicSharedMemorySize, SMEM_GEMM);
    cudaFuncSetAttribute(gemm_tc<2>, cudaFuncAttributeMaxDynamicSharedMemorySize, SMEM_GEMM);

    cvt_kernel<<<512, 256>>>(wqkv, cw_qkv, Lc * Cc * 3 * Cc);
    cvt_kernel<<<512, 256>>>(wo,   cw_o,   Lc * Cc * Cc);
    cvt_kernel<<<512, 256>>>(wfc,  cw_fc,  Lc * Cc * FFc);
    cvt_kernel<<<512, 256>>>(wpr,  cw_pr,  Lc * FFc * Cc);
    cvt_kernel<<<128, 256>>>(w_lm, cw_lm,  Cc * Vc);

    embed_kernel<<<NTOK, Cc>>>(idx, tok, pos, px);

    for (int l = 0; l < Lc; l++) {
        const float* Wq = cw_qkv + (size_t)l * Cc * 3 * Cc;
        const float* bq = bqkv + (size_t)l * 3 * Cc;
        const float* Wo = cw_o + (size_t)l * Cc * Cc;
        const float* bo_ = bo + (size_t)l * Cc;
        const float* Wf = cw_fc + (size_t)l * Cc * FFc;
        const float* bf = bfc + (size_t)l * FFc;
        const float* Wp = cw_pr + (size_t)l * FFc * Cc;
        const float* bp = bpr + (size_t)l * Cc;

        ln_kernel<<<NTOK, Cc>>>(px, ln1_g + (size_t)l * Cc, ln1_b + (size_t)l * Cc, pln);
        {
            dim3 grid((3 * Cc) / BN, NTOK / BM);
            gemm_tc<0><<<grid, 256, SMEM_GEMM>>>(pln, Wq, bq, nullptr, pqkv, NTOK, 3 * Cc, Cc);
        }
        {
            dim3 grid(Tc / ATQ, Hc, Bc);
            attn_flash<<<grid, 256>>>(pqkv, pln);
        }
        {
            dim3 grid(Cc / BN, NTOK / BM);
            gemm_tc<1><<<grid, 256, SMEM_GEMM>>>(pln, Wo, bo_, px, px, NTOK, Cc, Cc);
        }
        ln_kernel<<<NTOK, Cc>>>(px, ln2_g + (size_t)l * Cc, ln2_b + (size_t)l * Cc, pln);
        {
            dim3 grid(FFc / BN, NTOK / BM);
            gemm_tc<2><<<grid, 256, SMEM_GEMM>>>(pln, Wf, bf, nullptr, pff, NTOK, FFc, Cc);
        }
        {
            dim3 grid(Cc / BN, NTOK / BM);
            gemm_tc<1><<<grid, 256, SMEM_GEMM>>>(pff, Wp, bp, px, px, NTOK, Cc, FFc);
        }
    }

    ln_kernel<<<NTOK, Cc>>>(px, lnf_g, lnf_b, pln);
    {
        dim3 grid(Vc / BN, NTOK / BM);
        gemm_tc<0><<<grid, 256, SMEM_GEMM>>>(pln, cw_lm, nullptr, nullptr, out, NTOK, Vc, Cc);
    }
}

// round 8
// speedup vs baseline: 4.8484x; 1.1294x over previous
#include <cuda_runtime.h>
#include <cuda_fp16.h>
#include <math.h>
#include <stdint.h>

// ---- problem constants (gpt-small) ----
#define Lc 8
#define Hc 8
#define Cc 256
#define Vc 128
#define Tc 1024
#define Bc 32
#define Dh 32
#define FFc 1024
#define NTOK (Bc * Tc)   // 32768

// ---- scratch (device globals; no allocation allowed) ----
__device__ float g_x[(size_t)NTOK * Cc];         // residual stream (fp32)
__device__ float g_qkv[(size_t)NTOK * 3 * Cc];   // qkv (fp32)
__device__ __half g_h256[(size_t)NTOK * Cc];     // half activations: ln / attn-y
__device__ __half g_h1024[(size_t)NTOK * FFc];   // half activations: gelu(ff)

// fp16 TRANSPOSED weights ([N,K] row-major): qkv | wo | wfc | wpr | w_lm
#define W_QKV_OFF 0
#define W_O_OFF   (W_QKV_OFF + (size_t)Lc * Cc * 3 * Cc)
#define W_FC_OFF  (W_O_OFF   + (size_t)Lc * Cc * Cc)
#define W_PR_OFF  (W_FC_OFF  + (size_t)Lc * Cc * FFc)
#define W_LM_OFF  (W_PR_OFF  + (size_t)Lc * FFc * Cc)
#define W_TOTAL   (W_LM_OFF  + (size_t)Cc * Vc)
__device__ __half g_wh[W_TOTAL];

// ------------------------------------------------------------------
// helpers
// ------------------------------------------------------------------
__device__ __forceinline__ float gelu_f(float x) {
    float x3 = x * x * x;
    return 0.5f * x * (1.0f + tanhf(0.7978845608028654f * (x + 0.044715f * x3)));
}

__device__ __forceinline__ uint32_t smem_u32(const void* p) {
    uint32_t a;
    asm("{.reg .u64 t; cvta.to.shared.u64 t, %1; cvt.u32.u64 %0, t;}" : "=r"(a) : "l"(p));
    return a;
}

__device__ __forceinline__ void cp16(uint32_t dst, const void* src) {
    asm volatile("cp.async.cg.shared.global [%0], [%1], 16;\n" :: "r"(dst), "l"(src));
}

__device__ __forceinline__ void mma_f16(float* c, const uint32_t* a, const uint32_t* b) {
    asm volatile(
        "mma.sync.aligned.m16n8k16.row.col.f32.f16.f16.f32 "
        "{%0,%1,%2,%3}, {%4,%5,%6,%7}, {%8,%9}, {%0,%1,%2,%3};\n"
        : "+f"(c[0]), "+f"(c[1]), "+f"(c[2]), "+f"(c[3])
        : "r"(a[0]), "r"(a[1]), "r"(a[2]), "r"(a[3]), "r"(b[0]), "r"(b[1]));
}

// ------------------------------------------------------------------
// weight transpose + fp16 conversion: in fp32 [K,N] -> out fp16 [N,K]
// (once per call, off the hot path)
// ------------------------------------------------------------------
__global__ void cvtT_kernel(const float* __restrict__ in, __half* __restrict__ out,
                            int K, int N) {
    __shared__ float t[32][33];
    int k0 = blockIdx.y * 32, n0 = blockIdx.x * 32;
    const float* src = in + (size_t)blockIdx.z * K * N;
    __half* dst = out + (size_t)blockIdx.z * K * N;
    int tx = threadIdx.x, ty = threadIdx.y;  // 32 x 8
#pragma unroll
    for (int i = 0; i < 4; i++)
        t[ty + 8 * i][tx] = src[(size_t)(k0 + ty + 8 * i) * N + n0 + tx];
    __syncthreads();
#pragma unroll
    for (int i = 0; i < 4; i++)
        dst[(size_t)(n0 + ty + 8 * i) * K + k0 + tx] = __float2half(t[tx][ty + 8 * i]);
}

// ------------------------------------------------------------------
// Embedding
// ------------------------------------------------------------------
__global__ void embed_kernel(const int* __restrict__ idx,
                             const float* __restrict__ tok,
                             const float* __restrict__ pos,
                             float* __restrict__ x) {
    int n = blockIdx.x;
    int c = threadIdx.x;
    int token = idx[n];
    x[(size_t)n * Cc + c] = tok[(size_t)token * Cc + c] + pos[(size_t)(n % Tc) * Cc + c];
}

// ------------------------------------------------------------------
// LayerNorm: fp32 in -> fp16 out (feeds GEMM A operand)
// ------------------------------------------------------------------
__global__ void ln_kernel(const float* __restrict__ x,
                          const float* __restrict__ g,
                          const float* __restrict__ b,
                          __half* __restrict__ out) {
    int row = blockIdx.x;
    int tid = threadIdx.x;
    int w = tid >> 5, lane = tid & 31;
    float v = x[(size_t)row * Cc + tid];

    __shared__ float sm[8];
    __shared__ float sm2[8];

    float s = v;
#pragma unroll
    for (int o = 16; o; o >>= 1) s += __shfl_xor_sync(0xffffffffu, s, o);
    if (lane == 0) sm[w] = s;
    __syncthreads();
    float tot = 0.f;
#pragma unroll
    for (int i = 0; i < 8; i++) tot += sm[i];
    float mean = tot * (1.0f / Cc);

    float d = v - mean;
    float q = d * d;
#pragma unroll
    for (int o = 16; o; o >>= 1) q += __shfl_xor_sync(0xffffffffu, q, o);
    if (lane == 0) sm2[w] = q;
    __syncthreads();
    float vtot = 0.f;
#pragma unroll
    for (int i = 0; i < 8; i++) vtot += sm2[i];
    float var = vtot * (1.0f / Cc);

    out[(size_t)row * Cc + tid] = __float2half(d * rsqrtf(var + 1e-5f) * g[tid] + b[tid]);
}

// ------------------------------------------------------------------
// fp16 tensor-core GEMM: out[M,N] = A[M,K] @ Bt[N,K]^T (+bias)(+res)(+gelu)
// A fp16 [M,K] row-major, Bt fp16 [N,K] row-major (pre-transposed weights).
// BM=128 BN=128 BK=32, 256 threads (8 warps, 64x32 warp tile),
// mma.m16n8k16, fp32 accum, 2-stage cp.async pipeline, 2 CTAs/SM.
// MODE: 0 = +bias -> fp32 out;  1 = +bias+residual -> fp32 out;
//       2 = +bias+gelu -> fp16 out
// ------------------------------------------------------------------
#define BM 128
#define BN 128
#define BK 32
#define AST 40                       // halves per smem row (32 + 8 pad = 80B)
#define TILE_HALFS (128 * AST)       // per A or B tile
#define STAGE_HALFS (2 * TILE_HALFS)
#define SMEM_GEMM (2 * STAGE_HALFS * 2)   // bytes: 2 stages * (A+B) * sizeof(half) = 40960

template <int MODE, typename OutT>
__global__ __launch_bounds__(256, 2) void gemm_h(
    const __half* __restrict__ A, const __half* __restrict__ Bt,
    const float* __restrict__ bias, const float* __restrict__ res,
    OutT* __restrict__ out, int M, int N, int K) {
    extern __shared__ __half hsm[];
    // layout: [stage][A tile | B tile]
    __half* As[2] = { hsm, hsm + STAGE_HALFS };
    __half* Bs[2] = { hsm + TILE_HALFS, hsm + STAGE_HALFS + TILE_HALFS };

    int tid = threadIdx.x;
    int bm = blockIdx.y * BM;
    int bn = blockIdx.x * BN;
    int lane = tid & 31, wid = tid >> 5;
    int wm = (wid >> 2) * 64;   // warp M offset (0/64)
    int wn = (wid & 3) * 32;    // warp N offset (0/32/64/96)
    int grp = lane >> 2, tig = lane & 3;

    float acc[4][4][4];
#pragma unroll
    for (int i = 0; i < 4; i++)
#pragma unroll
        for (int j = 0; j < 4; j++)
#pragma unroll
            for (int k = 0; k < 4; k++) acc[i][j][k] = 0.f;

    uint32_t sA[2] = { smem_u32(As[0]), smem_u32(As[1]) };
    uint32_t sB[2] = { smem_u32(Bs[0]), smem_u32(Bs[1]) };

    int KT = K / BK;

    // copy one BK=32 stage: A 128x32 halves (8KB), B 128x32 halves (8KB)
    // 512 16B-chunks each -> 2 chunks/thread for A, 2 for B
    auto copy_stage = [&](int s, int buf) {
        int k0 = s * BK;
#pragma unroll
        for (int i = 0; i < 2; i++) {
            int id = tid + i * 256;        // 0..511
            int row = id >> 2;             // 0..127
            int ck = (id & 3) << 3;        // half-offset 0,8,16,24
            cp16(sA[buf] + (uint32_t)((row * AST + ck) * 2),
                 A + (size_t)(bm + row) * K + k0 + ck);
            cp16(sB[buf] + (uint32_t)((row * AST + ck) * 2),
                 Bt + (size_t)(bn + row) * K + k0 + ck);
        }
        asm volatile("cp.async.commit_group;\n" ::: "memory");
    };

    copy_stage(0, 0);

    for (int s = 0; s < KT; s++) {
        int buf = s & 1;
        asm volatile("cp.async.wait_group 0;\n" ::: "memory");
        __syncthreads();

        if (s + 1 < KT) copy_stage(s + 1, buf ^ 1);

        const __half* as = As[buf];
        const __half* bs = Bs[buf];
#pragma unroll
        for (int kk = 0; kk < 2; kk++) {
            int k0 = kk * 16;
            uint32_t a[4][4], b[4][2];
#pragma unroll
            for (int mi = 0; mi < 4; mi++) {
                int r = wm + mi * 16 + grp;
                a[mi][0] = *(const uint32_t*)(as + r * AST + k0 + tig * 2);
                a[mi][1] = *(const uint32_t*)(as + (r + 8) * AST + k0 + tig * 2);
                a[mi][2] = *(const uint32_t*)(as + r * AST + k0 + tig * 2 + 8);
                a[mi][3] = *(const uint32_t*)(as + (r + 8) * AST + k0 + tig * 2 + 8);
            }
#pragma unroll
            for (int ni = 0; ni < 4; ni++) {
                int c = wn + ni * 8 + grp;
                b[ni][0] = *(const uint32_t*)(bs + c * AST + k0 + tig * 2);
                b[ni][1] = *(const uint32_t*)(bs + c * AST + k0 + tig * 2 + 8);
            }
#pragma unroll
            for (int mi = 0; mi < 4; mi++)
#pragma unroll
                for (int ni = 0; ni < 4; ni++)
                    mma_f16(acc[mi][ni], a[mi], b[ni]);
        }
        __syncthreads();
    }

    // epilogue (C fragment: lane -> rows grp/grp+8, cols 2*tig, 2*tig+1)
#pragma unroll
    for (int mi = 0; mi < 4; mi++) {
        int r0 = bm + wm + mi * 16 + grp;
#pragma unroll
        for (int ni = 0; ni < 4; ni++) {
            int c0 = bn + wn + ni * 8 + 2 * tig;
            float v00 = acc[mi][ni][0], v01 = acc[mi][ni][1];
            float v10 = acc[mi][ni][2], v11 = acc[mi][ni][3];
            if (bias) {
                float b0 = bias[c0], b1 = bias[c0 + 1];
                v00 += b0; v01 += b1; v10 += b0; v11 += b1;
            }
            if (MODE == 1) {
                float2 r1 = *(const float2*)(res + (size_t)r0 * N + c0);
                float2 r2 = *(const float2*)(res + (size_t)(r0 + 8) * N + c0);
                v00 += r1.x; v01 += r1.y; v10 += r2.x; v11 += r2.y;
            }
            if (MODE == 2) {
                // gelu, then fp16 out
                __half2* o1 = (__half2*)((__half*)out + (size_t)r0 * N + c0);
                __half2* o2 = (__half2*)((__half*)out + (size_t)(r0 + 8) * N + c0);
                *o1 = __floats2half2_rn(gelu_f(v00), gelu_f(v01));
                *o2 = __floats2half2_rn(gelu_f(v10), gelu_f(v11));
            } else {
                float* op = (float*)out;
                *(float2*)(op + (size_t)r0 * N + c0) = make_float2(v00, v01);
                *(float2*)(op + (size_t)(r0 + 8) * N + c0) = make_float2(v10, v11);
            }
        }
    }
}

// ------------------------------------------------------------------
// Flash attention (SIMT, fp32 math): reads fp32 qkv, writes fp16 y
// ------------------------------------------------------------------
#define ATQ 256
#define ATK 64

__global__ __launch_bounds__(256) void attn_flash(const float* __restrict__ qkv,
                                                  __half* __restrict__ y) {
    int qi = blockIdx.x, h = blockIdx.y, b = blockIdx.z;
    int qbase = qi * ATQ;
    int tid = threadIdx.x;
    int q = qbase + tid;
    size_t rowbase = (size_t)b * Tc;

    __shared__ float Ks[ATK][32];
    __shared__ float Vs[ATK][32];

    float4 qreg[8];
    const float4* qp = (const float4*)(qkv + (rowbase + q) * (3 * Cc) + h * Dh);
#pragma unroll
    for (int j = 0; j < 8; j++) qreg[j] = qp[j];

    float o[32];
#pragma unroll
    for (int d = 0; d < 32; d++) o[d] = 0.f;
    float m = -INFINITY, l = 0.f;

    const float scale = 0.17677669529663687f;
    int nkt = (qbase + ATQ) / ATK;

    for (int kt = 0; kt < nkt; kt++) {
        int kbase = kt * ATK;
        bool masked = (kbase >= qbase);

        __syncthreads();
#pragma unroll
        for (int j = 0; j < 2; j++) {
            int i = tid + j * 256;
            int r = i >> 3, c = i & 7;
            const float* krow = qkv + (rowbase + kbase + r) * (3 * Cc) + Cc + h * Dh;
            const float* vrow = qkv + (rowbase + kbase + r) * (3 * Cc) + 2 * Cc + h * Dh;
            ((float4*)Ks[r])[c] = ((const float4*)krow)[c];
            ((float4*)Vs[r])[c] = ((const float4*)vrow)[c];
        }
        __syncthreads();

#pragma unroll 1
        for (int c0 = 0; c0 < ATK; c0 += 16) {
            float s[16];
#pragma unroll
            for (int kk = 0; kk < 16; kk++) {
                const float4* kr = (const float4*)Ks[c0 + kk];
                float acc = 0.f;
#pragma unroll
                for (int j = 0; j < 8; j++) {
                    float4 kv = kr[j];
                    acc += qreg[j].x * kv.x + qreg[j].y * kv.y
                         + qreg[j].z * kv.z + qreg[j].w * kv.w;
                }
                int key = kbase + c0 + kk;
                s[kk] = (!masked || key <= q) ? acc * scale : -INFINITY;
            }

            float cm = s[0];
#pragma unroll
            for (int kk = 1; kk < 16; kk++) cm = fmaxf(cm, s[kk]);

            if (cm > m) {
                float alpha = __expf(m - cm);
                l *= alpha;
#pragma unroll
                for (int d = 0; d < 32; d++) o[d] *= alpha;
                m = cm;
            }

#pragma unroll
            for (int kk = 0; kk < 16; kk++) {
                float p = __expf(s[kk] - m);
                l += p;
                const float4* vr = (const float4*)Vs[c0 + kk];
#pragma unroll
                for (int j = 0; j < 8; j++) {
                    float4 vv = vr[j];
                    o[4 * j + 0] += p * vv.x;
                    o[4 * j + 1] += p * vv.y;
                    o[4 * j + 2] += p * vv.z;
                    o[4 * j + 3] += p * vv.w;
                }
            }
        }
    }

    float inv = 1.0f / l;
    __half2* yp = (__half2*)(y + (rowbase + q) * Cc + h * Dh);
#pragma unroll
    for (int j = 0; j < 16; j++)
        yp[j] = __floats2half2_rn(o[2 * j] * inv, o[2 * j + 1] * inv);
}

// ------------------------------------------------------------------
// Host orchestration
// ------------------------------------------------------------------
extern "C" void kernel_launch(void* const* d_in, const int* in_sizes, int n_in,
                              void* d_out, int out_size) {
    const int*   idx    = (const int*)d_in[0];
    const float* tok    = (const float*)d_in[1];
    const float* pos    = (const float*)d_in[2];
    const float* ln1_g  = (const float*)d_in[3];
    const float* ln1_b  = (const float*)d_in[4];
    const float* wqkv   = (const float*)d_in[5];
    const float* bqkv   = (const float*)d_in[6];
    const float* wo     = (const float*)d_in[7];
    const float* bo     = (const float*)d_in[8];
    const float* ln2_g  = (const float*)d_in[9];
    const float* ln2_b  = (const float*)d_in[10];
    const float* wfc    = (const float*)d_in[11];
    const float* bfc    = (const float*)d_in[12];
    const float* wpr    = (const float*)d_in[13];
    const float* bpr    = (const float*)d_in[14];
    const float* lnf_g  = (const float*)d_in[15];
    const float* lnf_b  = (const float*)d_in[16];
    const float* w_lm   = (const float*)d_in[17];
    float* out = (float*)d_out;

    float *px, *pqkv;
    __half *ph256, *ph1024, *pwh;
    cudaGetSymbolAddress((void**)&px, g_x);
    cudaGetSymbolAddress((void**)&pqkv, g_qkv);
    cudaGetSymbolAddress((void**)&ph256, g_h256);
    cudaGetSymbolAddress((void**)&ph1024, g_h1024);
    cudaGetSymbolAddress((void**)&pwh, g_wh);

    __half* cw_qkv = pwh + W_QKV_OFF;
    __half* cw_o   = pwh + W_O_OFF;
    __half* cw_fc  = pwh + W_FC_OFF;
    __half* cw_pr  = pwh + W_PR_OFF;
    __half* cw_lm  = pwh + W_LM_OFF;

    cudaFuncSetAttribute(gemm_h<0, float>, cudaFuncAttributeMaxDynamicSharedMemorySize, SMEM_GEMM);
    cudaFuncSetAttribute(gemm_h<1, float>, cudaFuncAttributeMaxDynamicSharedMemorySize, SMEM_GEMM);
    cudaFuncSetAttribute(gemm_h<2, __half>, cudaFuncAttributeMaxDynamicSharedMemorySize, SMEM_GEMM);

    // weight transpose + fp16 conversion ([K,N] -> [N,K])
    dim3 tb(32, 8);
    cvtT_kernel<<<dim3(768 / 32, 256 / 32, Lc), tb>>>(wqkv, cw_qkv, 256, 768);
    cvtT_kernel<<<dim3(256 / 32, 256 / 32, Lc), tb>>>(wo,   cw_o,   256, 256);
    cvtT_kernel<<<dim3(1024 / 32, 256 / 32, Lc), tb>>>(wfc, cw_fc,  256, 1024);
    cvtT_kernel<<<dim3(256 / 32, 1024 / 32, Lc), tb>>>(wpr, cw_pr,  1024, 256);
    cvtT_kernel<<<dim3(128 / 32, 256 / 32, 1), tb>>>(w_lm,  cw_lm,  256, 128);

    embed_kernel<<<NTOK, Cc>>>(idx, tok, pos, px);

    for (int l = 0; l < Lc; l++) {
        const __half* Wq = cw_qkv + (size_t)l * Cc * 3 * Cc;
        const float*  bq = bqkv + (size_t)l * 3 * Cc;
        const __half* Wo = cw_o + (size_t)l * Cc * Cc;
        const float*  bo_ = bo + (size_t)l * Cc;
        const __half* Wf = cw_fc + (size_t)l * Cc * FFc;
        const float*  bf = bfc + (size_t)l * FFc;
        const __half* Wp = cw_pr + (size_t)l * FFc * Cc;
        const float*  bp = bpr + (size_t)l * Cc;

        ln_kernel<<<NTOK, Cc>>>(px, ln1_g + (size_t)l * Cc, ln1_b + (size_t)l * Cc, ph256);
        {   // qkv = ln @ Wq + bq   [32768, 768] fp32
            dim3 grid((3 * Cc) / BN, NTOK / BM);
            gemm_h<0, float><<<grid, 256, SMEM_GEMM>>>(ph256, Wq, bq, nullptr, pqkv, NTOK, 3 * Cc, Cc);
        }
        {   // attention -> y (fp16) into ph256
            dim3 grid(Tc / ATQ, Hc, Bc);
            attn_flash<<<grid, 256>>>(pqkv, ph256);
        }
        {   // x = x + y @ Wo + bo  (fp32)
            dim3 grid(Cc / BN, NTOK / BM);
            gemm_h<1, float><<<grid, 256, SMEM_GEMM>>>(ph256, Wo, bo_, px, px, NTOK, Cc, Cc);
        }
        ln_kernel<<<NTOK, Cc>>>(px, ln2_g + (size_t)l * Cc, ln2_b + (size_t)l * Cc, ph256);
        {   // ff = gelu(ln @ Wf + bf)  [32768, 1024] fp16
            dim3 grid(FFc / BN, NTOK / BM);
            gemm_h<2, __half><<<grid, 256, SMEM_GEMM>>>(ph256, Wf, bf, nullptr, ph1024, NTOK, FFc, Cc);
        }
        {   // x = x + ff @ Wp + bp  (fp32)
            dim3 grid(Cc / BN, NTOK / BM);
            gemm_h<1, float><<<grid, 256, SMEM_GEMM>>>(ph1024, Wp, bp, px, px, NTOK, Cc, FFc);
        }
    }

    ln_kernel<<<NTOK, Cc>>>(px, lnf_g, lnf_b, ph256);
    {   // logits = ln @ w_lm  [32768, 128] fp32
        dim3 grid(Vc / BN, NTOK / BM);
        gemm_h<0, float><<<grid, 256, SMEM_GEMM>>>(ph256, cw_lm, nullptr, nullptr, out, NTOK, Vc, Cc);
    }
}

// round 9
// speedup vs baseline: 5.0560x; 1.0428x over previous
#include <cuda_runtime.h>
#include <cuda_fp16.h>
#include <math.h>
#include <stdint.h>

// ---- problem constants (gpt-small) ----
#define Lc 8
#define Hc 8
#define Cc 256
#define Vc 128
#define Tc 1024
#define Bc 32
#define Dh 32
#define FFc 1024
#define NTOK (Bc * Tc)   // 32768

typedef unsigned long long ull;

// ---- scratch (device globals; no allocation allowed) ----
__device__ float g_x[(size_t)NTOK * Cc];         // residual stream (fp32)
__device__ float g_qkv[(size_t)NTOK * 3 * Cc];   // qkv (fp32)
__device__ __half g_h256[(size_t)NTOK * Cc];     // half activations: ln / attn-y
__device__ __half g_h1024[(size_t)NTOK * FFc];   // half activations: gelu(ff)

// fp16 TRANSPOSED weights ([N,K] row-major): qkv | wo | wfc | wpr | w_lm
#define W_QKV_OFF 0
#define W_O_OFF   (W_QKV_OFF + (size_t)Lc * Cc * 3 * Cc)
#define W_FC_OFF  (W_O_OFF   + (size_t)Lc * Cc * Cc)
#define W_PR_OFF  (W_FC_OFF  + (size_t)Lc * Cc * FFc)
#define W_LM_OFF  (W_PR_OFF  + (size_t)Lc * FFc * Cc)
#define W_TOTAL   (W_LM_OFF  + (size_t)Cc * Vc)
__device__ __half g_wh[W_TOTAL];

// ------------------------------------------------------------------
// helpers
// ------------------------------------------------------------------
__device__ __forceinline__ float gelu_f(float x) {
    float x3 = x * x * x;
    return 0.5f * x * (1.0f + tanhf(0.7978845608028654f * (x + 0.044715f * x3)));
}

__device__ __forceinline__ uint32_t smem_u32(const void* p) {
    uint32_t a;
    asm("{.reg .u64 t; cvta.to.shared.u64 t, %1; cvt.u32.u64 %0, t;}" : "=r"(a) : "l"(p));
    return a;
}

__device__ __forceinline__ void cp16(uint32_t dst, const void* src) {
    asm volatile("cp.async.cg.shared.global [%0], [%1], 16;\n" :: "r"(dst), "l"(src));
}

__device__ __forceinline__ void mma_f16(float* c, const uint32_t* a, const uint32_t* b) {
    asm volatile(
        "mma.sync.aligned.m16n8k16.row.col.f32.f16.f16.f32 "
        "{%0,%1,%2,%3}, {%4,%5,%6,%7}, {%8,%9}, {%0,%1,%2,%3};\n"
        : "+f"(c[0]), "+f"(c[1]), "+f"(c[2]), "+f"(c[3])
        : "r"(a[0]), "r"(a[1]), "r"(a[2]), "r"(a[3]), "r"(b[0]), "r"(b[1]));
}

__device__ __forceinline__ void ldsm_x4(uint32_t* r, uint32_t addr) {
    asm volatile("ldmatrix.sync.aligned.m8n8.x4.shared.b16 {%0,%1,%2,%3}, [%4];"
                 : "=r"(r[0]), "=r"(r[1]), "=r"(r[2]), "=r"(r[3]) : "r"(addr));
}
__device__ __forceinline__ void ldsm_x2(uint32_t* r, uint32_t addr) {
    asm volatile("ldmatrix.sync.aligned.m8n8.x2.shared.b16 {%0,%1}, [%2];"
                 : "=r"(r[0]), "=r"(r[1]) : "r"(addr));
}

// packed f32x2 ops
__device__ __forceinline__ ull pack2(float lo, float hi) {
    ull r; asm("mov.b64 %0, {%1,%2};" : "=l"(r) : "f"(lo), "f"(hi)); return r;
}
__device__ __forceinline__ void unpack2(ull v, float& lo, float& hi) {
    asm("mov.b64 {%0,%1}, %2;" : "=f"(lo), "=f"(hi) : "l"(v));
}
#define FMA2(d, a, b, c) asm("fma.rn.f32x2 %0, %1, %2, %3;" : "=l"(d) : "l"(a), "l"(b), "l"(c))
#define MUL2(d, a, b)    asm("mul.rn.f32x2 %0, %1, %2;" : "=l"(d) : "l"(a), "l"(b))

// ------------------------------------------------------------------
// weight transpose + fp16 conversion: fp32 [K,N] -> fp16 [N,K]
// ------------------------------------------------------------------
__global__ void cvtT_kernel(const float* __restrict__ in, __half* __restrict__ out,
                            int K, int N) {
    __shared__ float t[32][33];
    int k0 = blockIdx.y * 32, n0 = blockIdx.x * 32;
    const float* src = in + (size_t)blockIdx.z * K * N;
    __half* dst = out + (size_t)blockIdx.z * K * N;
    int tx = threadIdx.x, ty = threadIdx.y;  // 32 x 8
#pragma unroll
    for (int i = 0; i < 4; i++)
        t[ty + 8 * i][tx] = src[(size_t)(k0 + ty + 8 * i) * N + n0 + tx];
    __syncthreads();
#pragma unroll
    for (int i = 0; i < 4; i++)
        dst[(size_t)(n0 + ty + 8 * i) * K + k0 + tx] = __float2half(t[tx][ty + 8 * i]);
}

// ------------------------------------------------------------------
// Embedding
// ------------------------------------------------------------------
__global__ void embed_kernel(const int* __restrict__ idx,
                             const float* __restrict__ tok,
                             const float* __restrict__ pos,
                             float* __restrict__ x) {
    int n = blockIdx.x;
    int c = threadIdx.x;
    int token = idx[n];
    x[(size_t)n * Cc + c] = tok[(size_t)token * Cc + c] + pos[(size_t)(n % Tc) * Cc + c];
}

// ------------------------------------------------------------------
// LayerNorm: fp32 in -> fp16 out
// ------------------------------------------------------------------
__global__ void ln_kernel(const float* __restrict__ x,
                          const float* __restrict__ g,
                          const float* __restrict__ b,
                          __half* __restrict__ out) {
    int row = blockIdx.x;
    int tid = threadIdx.x;
    int w = tid >> 5, lane = tid & 31;
    float v = x[(size_t)row * Cc + tid];

    __shared__ float sm[8];
    __shared__ float sm2[8];

    float s = v;
#pragma unroll
    for (int o = 16; o; o >>= 1) s += __shfl_xor_sync(0xffffffffu, s, o);
    if (lane == 0) sm[w] = s;
    __syncthreads();
    float tot = 0.f;
#pragma unroll
    for (int i = 0; i < 8; i++) tot += sm[i];
    float mean = tot * (1.0f / Cc);

    float d = v - mean;
    float q = d * d;
#pragma unroll
    for (int o = 16; o; o >>= 1) q += __shfl_xor_sync(0xffffffffu, q, o);
    if (lane == 0) sm2[w] = q;
    __syncthreads();
    float vtot = 0.f;
#pragma unroll
    for (int i = 0; i < 8; i++) vtot += sm2[i];
    float var = vtot * (1.0f / Cc);

    out[(size_t)row * Cc + tid] = __float2half(d * rsqrtf(var + 1e-5f) * g[tid] + b[tid]);
}

// ------------------------------------------------------------------
// fp16 tensor-core GEMM with ldmatrix fragment loads.
// out[M,N] = A[M,K] @ Bt[N,K]^T (+bias)(+res)(+gelu)
// BM=128 BN=128 BK=32, 256 threads, 64x32 warp tile, m16n8k16, fp32 accum,
// 2-stage cp.async pipeline, one barrier per k-iter, 2 CTAs/SM.
// MODE: 0=+bias->fp32, 1=+bias+res->fp32, 2=+bias+gelu->fp16
// ------------------------------------------------------------------
#define BM 128
#define BN 128
#define BK 32
#define AST 40                       // halves per smem row (80B) - conflict-free for ldmatrix
#define TILE_HALFS (128 * AST)
#define STAGE_HALFS (2 * TILE_HALFS)
#define SMEM_GEMM (2 * STAGE_HALFS * 2)   // 40960 bytes

template <int MODE, typename OutT>
__global__ __launch_bounds__(256, 2) void gemm_h(
    const __half* __restrict__ A, const __half* __restrict__ Bt,
    const float* __restrict__ bias, const float* __restrict__ res,
    OutT* __restrict__ out, int M, int N, int K) {
    extern __shared__ __half hsm[];
    __half* As[2] = { hsm, hsm + STAGE_HALFS };
    __half* Bs[2] = { hsm + TILE_HALFS, hsm + STAGE_HALFS + TILE_HALFS };

    int tid = threadIdx.x;
    int bm = blockIdx.y * BM;
    int bn = blockIdx.x * BN;
    int lane = tid & 31, wid = tid >> 5;
    int wm = (wid >> 2) * 64;   // warp M offset (0/64)
    int wn = (wid & 3) * 32;    // warp N offset (0/32/64/96)
    int grp = lane >> 2, tig = lane & 3;

    float acc[4][4][4];
#pragma unroll
    for (int i = 0; i < 4; i++)
#pragma unroll
        for (int j = 0; j < 4; j++)
#pragma unroll
            for (int k = 0; k < 4; k++) acc[i][j][k] = 0.f;

    uint32_t sA[2] = { smem_u32(As[0]), smem_u32(As[1]) };
    uint32_t sB[2] = { smem_u32(Bs[0]), smem_u32(Bs[1]) };

    // ldmatrix per-thread address offsets (bytes), buffer-independent
    uint32_t offA[4], offB[4];
    {
        int l16 = lane & 15;
        int ka = (lane >> 4) << 3;          // 0 or 8 halves
#pragma unroll
        for (int mi = 0; mi < 4; mi++)
            offA[mi] = (uint32_t)(((wm + mi * 16 + l16) * AST + ka) * 2);
        int l8 = lane & 7;
        int kb = ((lane >> 3) & 1) << 3;    // 0 or 8 halves
#pragma unroll
        for (int ni = 0; ni < 4; ni++)
            offB[ni] = (uint32_t)(((wn + ni * 8 + l8) * AST + kb) * 2);
    }

    int KT = K / BK;

    auto copy_stage = [&](int s, int buf) {
        int k0 = s * BK;
#pragma unroll
        for (int i = 0; i < 2; i++) {
            int id = tid + i * 256;        // 0..511
            int row = id >> 2;             // 0..127
            int ck = (id & 3) << 3;        // half-offset 0,8,16,24
            cp16(sA[buf] + (uint32_t)((row * AST + ck) * 2),
                 A + (size_t)(bm + row) * K + k0 + ck);
            cp16(sB[buf] + (uint32_t)((row * AST + ck) * 2),
                 Bt + (size_t)(bn + row) * K + k0 + ck);
        }
        asm volatile("cp.async.commit_group;\n" ::: "memory");
    };

    copy_stage(0, 0);

    for (int s = 0; s < KT; s++) {
        int buf = s & 1;
        asm volatile("cp.async.wait_group 0;\n" ::: "memory");
        __syncthreads();    // data(s) ready in all warps; compute(s-1) done everywhere

        if (s + 1 < KT) copy_stage(s + 1, buf ^ 1);

#pragma unroll
        for (int kk = 0; kk < 2; kk++) {
            uint32_t koff = (uint32_t)(kk * 32);   // 16 halves = 32 bytes
            uint32_t a[4][4], b[4][2];
#pragma unroll
            for (int mi = 0; mi < 4; mi++) ldsm_x4(a[mi], sA[buf] + offA[mi] + koff);
#pragma unroll
            for (int ni = 0; ni < 4; ni++) ldsm_x2(b[ni], sB[buf] + offB[ni] + koff);
#pragma unroll
            for (int mi = 0; mi < 4; mi++)
#pragma unroll
                for (int ni = 0; ni < 4; ni++)
                    mma_f16(acc[mi][ni], a[mi], b[ni]);
        }
    }

    __syncthreads();  // all compute done before epilogue (no buffer hazard, but cheap)

    // epilogue (C fragment: lane -> rows grp/grp+8, cols 2*tig, 2*tig+1)
#pragma unroll
    for (int mi = 0; mi < 4; mi++) {
        int r0 = bm + wm + mi * 16 + grp;
#pragma unroll
        for (int ni = 0; ni < 4; ni++) {
            int c0 = bn + wn + ni * 8 + 2 * tig;
            float v00 = acc[mi][ni][0], v01 = acc[mi][ni][1];
            float v10 = acc[mi][ni][2], v11 = acc[mi][ni][3];
            if (bias) {
                float b0 = bias[c0], b1 = bias[c0 + 1];
                v00 += b0; v01 += b1; v10 += b0; v11 += b1;
            }
            if (MODE == 1) {
                float2 r1 = *(const float2*)(res + (size_t)r0 * N + c0);
                float2 r2 = *(const float2*)(res + (size_t)(r0 + 8) * N + c0);
                v00 += r1.x; v01 += r1.y; v10 += r2.x; v11 += r2.y;
            }
            if (MODE == 2) {
                __half2* o1 = (__half2*)((__half*)out + (size_t)r0 * N + c0);
                __half2* o2 = (__half2*)((__half*)out + (size_t)(r0 + 8) * N + c0);
                *o1 = __floats2half2_rn(gelu_f(v00), gelu_f(v01));
                *o2 = __floats2half2_rn(gelu_f(v10), gelu_f(v11));
            } else {
                float* op = (float*)out;
                *(float2*)(op + (size_t)r0 * N + c0) = make_float2(v00, v01);
                *(float2*)(op + (size_t)(r0 + 8) * N + c0) = make_float2(v10, v11);
            }
        }
    }
}

// ------------------------------------------------------------------
// Flash attention (SIMT, packed f32x2 math): fp32 qkv in, fp16 y out.
// One block = 256 queries of one (b,h); one thread = one query.
// ------------------------------------------------------------------
#define ATQ 256
#define ATK 64

__global__ __launch_bounds__(256) void attn_flash(const float* __restrict__ qkv,
                                                  __half* __restrict__ y) {
    int qi = blockIdx.x, h = blockIdx.y, b = blockIdx.z;
    int qbase = qi * ATQ;
    int tid = threadIdx.x;
    int q = qbase + tid;
    size_t rowbase = (size_t)b * Tc;

    __shared__ float Ks[ATK][32];
    __shared__ float Vs[ATK][32];

    // query into 16 packed f32x2 registers
    ull q2[16];
    {
        const ulonglong2* qp = (const ulonglong2*)(qkv + (rowbase + q) * (3 * Cc) + h * Dh);
#pragma unroll
        for (int j = 0; j < 8; j++) {
            ulonglong2 u = qp[j];
            q2[2 * j] = u.x;
            q2[2 * j + 1] = u.y;
        }
    }

    ull o2[16];
    const ull zz = pack2(0.f, 0.f);
#pragma unroll
    for (int j = 0; j < 16; j++) o2[j] = zz;
    float m = -INFINITY, l = 0.f;

    const float scale = 0.17677669529663687f;
    int nkt = (qbase + ATQ) / ATK;

    for (int kt = 0; kt < nkt; kt++) {
        int kbase = kt * ATK;
        bool masked = (kbase >= qbase);

        __syncthreads();
#pragma unroll
        for (int j = 0; j < 2; j++) {
            int i = tid + j * 256;
            int r = i >> 3, c = i & 7;
            const float* krow = qkv + (rowbase + kbase + r) * (3 * Cc) + Cc + h * Dh;
            const float* vrow = qkv + (rowbase + kbase + r) * (3 * Cc) + 2 * Cc + h * Dh;
            ((float4*)Ks[r])[c] = ((const float4*)krow)[c];
            ((float4*)Vs[r])[c] = ((const float4*)vrow)[c];
        }
        __syncthreads();

#pragma unroll 1
        for (int c0 = 0; c0 < ATK; c0 += 16) {
            float s[16];
#pragma unroll
            for (int kk = 0; kk < 16; kk++) {
                const ulonglong2* kr = (const ulonglong2*)Ks[c0 + kk];
                ull acc_a = zz, acc_b = zz;
#pragma unroll
                for (int j = 0; j < 8; j++) {
                    ulonglong2 kv = kr[j];
                    FMA2(acc_a, q2[2 * j], kv.x, acc_a);
                    FMA2(acc_b, q2[2 * j + 1], kv.y, acc_b);
                }
                float a0, a1, b0, b1;
                unpack2(acc_a, a0, a1);
                unpack2(acc_b, b0, b1);
                float acc = (a0 + b0) + (a1 + b1);
                int key = kbase + c0 + kk;
                s[kk] = (!masked || key <= q) ? acc * scale : -INFINITY;
            }

            float cm = s[0];
#pragma unroll
            for (int kk = 1; kk < 16; kk++) cm = fmaxf(cm, s[kk]);

            if (cm > m) {
                float alpha = __expf(m - cm);   // exp(-inf)=0 on first update
                l *= alpha;
                ull al2 = pack2(alpha, alpha);
#pragma unroll
                for (int j = 0; j < 16; j++) MUL2(o2[j], o2[j], al2);
                m = cm;
            }

#pragma unroll
            for (int kk = 0; kk < 16; kk++) {
                float p = __expf(s[kk] - m);    // masked -> 0
                l += p;
                ull p2 = pack2(p, p);
                const ulonglong2* vr = (const ulonglong2*)Vs[c0 + kk];
#pragma unroll
                for (int j = 0; j < 8; j++) {
                    ulonglong2 vv = vr[j];
                    FMA2(o2[2 * j], p2, vv.x, o2[2 * j]);
                    FMA2(o2[2 * j + 1], p2, vv.y, o2[2 * j + 1]);
                }
            }
        }
    }

    float inv = 1.0f / l;
    __half2* yp = (__half2*)(y + (rowbase + q) * Cc + h * Dh);
#pragma unroll
    for (int j = 0; j < 16; j++) {
        float lo, hi;
        unpack2(o2[j], lo, hi);
        yp[j] = __floats2half2_rn(lo * inv, hi * inv);
    }
}

// ------------------------------------------------------------------
// Host orchestration
// ------------------------------------------------------------------
extern "C" void kernel_launch(void* const* d_in, const int* in_sizes, int n_in,
                              void* d_out, int out_size) {
    const int*   idx    = (const int*)d_in[0];
    const float* tok    = (const float*)d_in[1];
    const float* pos    = (const float*)d_in[2];
    const float* ln1_g  = (const float*)d_in[3];
    const float* ln1_b  = (const float*)d_in[4];
    const float* wqkv   = (const float*)d_in[5];
    const float* bqkv   = (const float*)d_in[6];
    const float* wo     = (const float*)d_in[7];
    const float* bo     = (const float*)d_in[8];
    const float* ln2_g  = (const float*)d_in[9];
    const float* ln2_b  = (const float*)d_in[10];
    const float* wfc    = (const float*)d_in[11];
    const float* bfc    = (const float*)d_in[12];
    const float* wpr    = (const float*)d_in[13];
    const float* bpr    = (const float*)d_in[14];
    const float* lnf_g  = (const float*)d_in[15];
    const float* lnf_b  = (const float*)d_in[16];
    const float* w_lm   = (const float*)d_in[17];
    float* out = (float*)d_out;

    float *px, *pqkv;
    __half *ph256, *ph1024, *pwh;
    cudaGetSymbolAddress((void**)&px, g_x);
    cudaGetSymbolAddress((void**)&pqkv, g_qkv);
    cudaGetSymbolAddress((void**)&ph256, g_h256);
    cudaGetSymbolAddress((void**)&ph1024, g_h1024);
    cudaGetSymbolAddress((void**)&pwh, g_wh);

    __half* cw_qkv = pwh + W_QKV_OFF;
    __half* cw_o   = pwh + W_O_OFF;
    __half* cw_fc  = pwh + W_FC_OFF;
    __half* cw_pr  = pwh + W_PR_OFF;
    __half* cw_lm  = pwh + W_LM_OFF;

    cudaFuncSetAttribute(gemm_h<0, float>, cudaFuncAttributeMaxDynamicSharedMemorySize, SMEM_GEMM);
    cudaFuncSetAttribute(gemm_h<1, float>, cudaFuncAttributeMaxDynamicSharedMemorySize, SMEM_GEMM);
    cudaFuncSetAttribute(gemm_h<2, __half>, cudaFuncAttributeMaxDynamicSharedMemorySize, SMEM_GEMM);

    dim3 tb(32, 8);
    cvtT_kernel<<<dim3(768 / 32, 256 / 32, Lc), tb>>>(wqkv, cw_qkv, 256, 768);
    cvtT_kernel<<<dim3(256 / 32, 256 / 32, Lc), tb>>>(wo,   cw_o,   256, 256);
    cvtT_kernel<<<dim3(1024 / 32, 256 / 32, Lc), tb>>>(wfc, cw_fc,  256, 1024);
    cvtT_kernel<<<dim3(256 / 32, 1024 / 32, Lc), tb>>>(wpr, cw_pr,  1024, 256);
    cvtT_kernel<<<dim3(128 / 32, 256 / 32, 1), tb>>>(w_lm,  cw_lm,  256, 128);

    embed_kernel<<<NTOK, Cc>>>(idx, tok, pos, px);

    for (int l = 0; l < Lc; l++) {
        const __half* Wq = cw_qkv + (size_t)l * Cc * 3 * Cc;
        const float*  bq = bqkv + (size_t)l * 3 * Cc;
        const __half* Wo = cw_o + (size_t)l * Cc * Cc;
        const float*  bo_ = bo + (size_t)l * Cc;
        const __half* Wf = cw_fc + (size_t)l * Cc * FFc;
        const float*  bf = bfc + (size_t)l * FFc;
        const __half* Wp = cw_pr + (size_t)l * FFc * Cc;
        const float*  bp = bpr + (size_t)l * Cc;

        ln_kernel<<<NTOK, Cc>>>(px, ln1_g + (size_t)l * Cc, ln1_b + (size_t)l * Cc, ph256);
        {   // qkv = ln @ Wq + bq   [32768, 768] fp32
            dim3 grid((3 * Cc) / BN, NTOK / BM);
            gemm_h<0, float><<<grid, 256, SMEM_GEMM>>>(ph256, Wq, bq, nullptr, pqkv, NTOK, 3 * Cc, Cc);
        }
        {   // attention -> y (fp16) into ph256
            dim3 grid(Tc / ATQ, Hc, Bc);
            attn_flash<<<grid, 256>>>(pqkv, ph256);
        }
        {   // x = x + y @ Wo + bo  (fp32)
            dim3 grid(Cc / BN, NTOK / BM);
            gemm_h<1, float><<<grid, 256, SMEM_GEMM>>>(ph256, Wo, bo_, px, px, NTOK, Cc, Cc);
        }
        ln_kernel<<<NTOK, Cc>>>(px, ln2_g + (size_t)l * Cc, ln2_b + (size_t)l * Cc, ph256);
        {   // ff = gelu(ln @ Wf + bf)  [32768, 1024] fp16
            dim3 grid(FFc / BN, NTOK / BM);
            gemm_h<2, __half><<<grid, 256, SMEM_GEMM>>>(ph256, Wf, bf, nullptr, ph1024, NTOK, FFc, Cc);
        }
        {   // x = x + ff @ Wp + bp  (fp32)
            dim3 grid(Cc / BN, NTOK / BM);
            gemm_h<1, float><<<grid, 256, SMEM_GEMM>>>(ph1024, Wp, bp, px, px, NTOK, Cc, FFc);
        }
    }

    ln_kernel<<<NTOK, Cc>>>(px, lnf_g, lnf_b, ph256);
    {   // logits = ln @ w_lm  [32768, 128] fp32
        dim3 grid(Vc / BN, NTOK / BM);
        gemm_h<0, float><<<grid, 256, SMEM_GEMM>>>(ph256, cw_lm, nullptr, nullptr, out, NTOK, Vc, Cc);
    }
}

// round 11
// speedup vs baseline: 5.0639x; 1.0016x over previous
#include <cuda_runtime.h>
#include <cuda_fp16.h>
#include <math.h>
#include <stdint.h>

// ---- problem constants (gpt-small) ----
#define Lc 8
#define Hc 8
#define Cc 256
#define Vc 128
#define Tc 1024
#define Bc 32
#define Dh 32
#define FFc 1024
#define NTOK (Bc * Tc)   // 32768

typedef unsigned long long ull;

// ---- scratch (device globals; no allocation allowed) ----
__device__ float g_x[(size_t)NTOK * Cc];         // residual stream (fp32)
__device__ float g_qkv[(size_t)NTOK * 3 * Cc];   // qkv (fp32)
__device__ __half g_h256[(size_t)NTOK * Cc];     // half activations: ln / attn-y
__device__ __half g_h1024[(size_t)NTOK * FFc];   // half activations: gelu(ff)

// fp16 TRANSPOSED weights ([N,K] row-major): qkv | wo | wfc | wpr | w_lm
#define W_QKV_OFF 0
#define W_O_OFF   (W_QKV_OFF + (size_t)Lc * Cc * 3 * Cc)
#define W_FC_OFF  (W_O_OFF   + (size_t)Lc * Cc * Cc)
#define W_PR_OFF  (W_FC_OFF  + (size_t)Lc * Cc * FFc)
#define W_LM_OFF  (W_PR_OFF  + (size_t)Lc * FFc * Cc)
#define W_TOTAL   (W_LM_OFF  + (size_t)Cc * Vc)
__device__ __half g_wh[W_TOTAL];

// ------------------------------------------------------------------
// helpers
// ------------------------------------------------------------------
__device__ __forceinline__ float gelu_f(float x) {
    float x3 = x * x * x;
    return 0.5f * x * (1.0f + tanhf(0.7978845608028654f * (x + 0.044715f * x3)));
}

__device__ __forceinline__ uint32_t smem_u32(const void* p) {
    uint32_t a;
    asm("{.reg .u64 t; cvta.to.shared.u64 t, %1; cvt.u32.u64 %0, t;}" : "=r"(a) : "l"(p));
    return a;
}

__device__ __forceinline__ void cp16(uint32_t dst, const void* src) {
    asm volatile("cp.async.cg.shared.global [%0], [%1], 16;\n" :: "r"(dst), "l"(src));
}

__device__ __forceinline__ void mma_f16(float* c, const uint32_t* a, const uint32_t* b) {
    asm volatile(
        "mma.sync.aligned.m16n8k16.row.col.f32.f16.f16.f32 "
        "{%0,%1,%2,%3}, {%4,%5,%6,%7}, {%8,%9}, {%0,%1,%2,%3};\n"
        : "+f"(c[0]), "+f"(c[1]), "+f"(c[2]), "+f"(c[3])
        : "r"(a[0]), "r"(a[1]), "r"(a[2]), "r"(a[3]), "r"(b[0]), "r"(b[1]));
}

__device__ __forceinline__ void ldsm_x4(uint32_t* r, uint32_t addr) {
    asm volatile("ldmatrix.sync.aligned.m8n8.x4.shared.b16 {%0,%1,%2,%3}, [%4];"
                 : "=r"(r[0]), "=r"(r[1]), "=r"(r[2]), "=r"(r[3]) : "r"(addr));
}
__device__ __forceinline__ void ldsm_x2(uint32_t* r, uint32_t addr) {
    asm volatile("ldmatrix.sync.aligned.m8n8.x2.shared.b16 {%0,%1}, [%2];"
                 : "=r"(r[0]), "=r"(r[1]) : "r"(addr));
}

// packed f32x2 ops
__device__ __forceinline__ ull pack2(float lo, float hi) {
    ull r; asm("mov.b64 %0, {%1,%2};" : "=l"(r) : "f"(lo), "f"(hi)); return r;
}
__device__ __forceinline__ void unpack2(ull v, float& lo, float& hi) {
    asm("mov.b64 {%0,%1}, %2;" : "=f"(lo), "=f"(hi) : "l"(v));
}
#define FMA2(d, a, b, c) asm("fma.rn.f32x2 %0, %1, %2, %3;" : "=l"(d) : "l"(a), "l"(b), "l"(c))
#define MUL2(d, a, b)    asm("mul.rn.f32x2 %0, %1, %2;" : "=l"(d) : "l"(a), "l"(b))

// ------------------------------------------------------------------
// weight transpose + fp16 conversion: fp32 [K,N] -> fp16 [N,K]
// ------------------------------------------------------------------
__global__ void cvtT_kernel(const float* __restrict__ in, __half* __restrict__ out,
                            int K, int N) {
    __shared__ float t[32][33];
    int k0 = blockIdx.y * 32, n0 = blockIdx.x * 32;
    const float* src = in + (size_t)blockIdx.z * K * N;
    __half* dst = out + (size_t)blockIdx.z * K * N;
    int tx = threadIdx.x, ty = threadIdx.y;  // 32 x 8
#pragma unroll
    for (int i = 0; i < 4; i++)
        t[ty + 8 * i][tx] = src[(size_t)(k0 + ty + 8 * i) * N + n0 + tx];
    __syncthreads();
#pragma unroll
    for (int i = 0; i < 4; i++)
        dst[(size_t)(n0 + ty + 8 * i) * K + k0 + tx] = __float2half(t[tx][ty + 8 * i]);
}

// ------------------------------------------------------------------
// Embedding
// ------------------------------------------------------------------
__global__ void embed_kernel(const int* __restrict__ idx,
                             const float* __restrict__ tok,
                             const float* __restrict__ pos,
                             float* __restrict__ x) {
    int n = blockIdx.x;
    int c = threadIdx.x;
    int token = idx[n];
    x[(size_t)n * Cc + c] = tok[(size_t)token * Cc + c] + pos[(size_t)(n % Tc) * Cc + c];
}

// ------------------------------------------------------------------
// LayerNorm: fp32 in -> fp16 out
// ------------------------------------------------------------------
__global__ void ln_kernel(const float* __restrict__ x,
                          const float* __restrict__ g,
                          const float* __restrict__ b,
                          __half* __restrict__ out) {
    int row = blockIdx.x;
    int tid = threadIdx.x;
    int w = tid >> 5, lane = tid & 31;
    float v = x[(size_t)row * Cc + tid];

    __shared__ float sm[8];
    __shared__ float sm2[8];

    float s = v;
#pragma unroll
    for (int o = 16; o; o >>= 1) s += __shfl_xor_sync(0xffffffffu, s, o);
    if (lane == 0) sm[w] = s;
    __syncthreads();
    float tot = 0.f;
#pragma unroll
    for (int i = 0; i < 8; i++) tot += sm[i];
    float mean = tot * (1.0f / Cc);

    float d = v - mean;
    float q = d * d;
#pragma unroll
    for (int o = 16; o; o >>= 1) q += __shfl_xor_sync(0xffffffffu, q, o);
    if (lane == 0) sm2[w] = q;
    __syncthreads();
    float vtot = 0.f;
#pragma unroll
    for (int i = 0; i < 8; i++) vtot += sm2[i];
    float var = vtot * (1.0f / Cc);

    out[(size_t)row * Cc + tid] = __float2half(d * rsqrtf(var + 1e-5f) * g[tid] + b[tid]);
}

// ------------------------------------------------------------------
// fp16 tensor-core GEMM with ldmatrix fragment loads.
// out[M,N] = A[M,K] @ Bt[N,K]^T (+bias)(+res)(+gelu)
// BM=128 BN=128 BK=32, 256 threads, 64x32 warp tile, m16n8k16, fp32 accum,
// 2-stage cp.async pipeline, one barrier per k-iter, 2 CTAs/SM.
// MODE: 0=+bias->fp32, 1=+bias+res->fp32, 2=+bias+gelu->fp16
// ------------------------------------------------------------------
#define BM 128
#define BN 128
#define BK 32
#define AST 40                       // halves per smem row (80B) - conflict-free for ldmatrix
#define TILE_HALFS (128 * AST)
#define STAGE_HALFS (2 * TILE_HALFS)
#define SMEM_GEMM (2 * STAGE_HALFS * 2)   // 40960 bytes

template <int MODE, typename OutT>
__global__ __launch_bounds__(256, 2) void gemm_h(
    const __half* __restrict__ A, const __half* __restrict__ Bt,
    const float* __restrict__ bias, const float* __restrict__ res,
    OutT* __restrict__ out, int M, int N, int K) {
    extern __shared__ __half hsm[];
    __half* As[2] = { hsm, hsm + STAGE_HALFS };
    __half* Bs[2] = { hsm + TILE_HALFS, hsm + STAGE_HALFS + TILE_HALFS };

    int tid = threadIdx.x;
    int bm = blockIdx.y * BM;
    int bn = blockIdx.x * BN;
    int lane = tid & 31, wid = tid >> 5;
    int wm = (wid >> 2) * 64;   // warp M offset (0/64)
    int wn = (wid & 3) * 32;    // warp N offset (0/32/64/96)
    int grp = lane >> 2, tig = lane & 3;

    float acc[4][4][4];
#pragma unroll
    for (int i = 0; i < 4; i++)
#pragma unroll
        for (int j = 0; j < 4; j++)
#pragma unroll
            for (int k = 0; k < 4; k++) acc[i][j][k] = 0.f;

    uint32_t sA[2] = { smem_u32(As[0]), smem_u32(As[1]) };
    uint32_t sB[2] = { smem_u32(Bs[0]), smem_u32(Bs[1]) };

    // ldmatrix per-thread address offsets (bytes), buffer-independent
    uint32_t offA[4], offB[4];
    {
        int l16 = lane & 15;
        int ka = (lane >> 4) << 3;          // 0 or 8 halves
#pragma unroll
        for (int mi = 0; mi < 4; mi++)
            offA[mi] = (uint32_t)(((wm + mi * 16 + l16) * AST + ka) * 2);
        int l8 = lane & 7;
        int kb = ((lane >> 3) & 1) << 3;    // 0 or 8 halves
#pragma unroll
        for (int ni = 0; ni < 4; ni++)
            offB[ni] = (uint32_t)(((wn + ni * 8 + l8) * AST + kb) * 2);
    }

    int KT = K / BK;

    auto copy_stage = [&](int s, int buf) {
        int k0 = s * BK;
#pragma unroll
        for (int i = 0; i < 2; i++) {
            int id = tid + i * 256;        // 0..511
            int row = id >> 2;             // 0..127
            int ck = (id & 3) << 3;        // half-offset 0,8,16,24
            cp16(sA[buf] + (uint32_t)((row * AST + ck) * 2),
                 A + (size_t)(bm + row) * K + k0 + ck);
            cp16(sB[buf] + (uint32_t)((row * AST + ck) * 2),
                 Bt + (size_t)(bn + row) * K + k0 + ck);
        }
        asm volatile("cp.async.commit_group;\n" ::: "memory");
    };

    copy_stage(0, 0);

    for (int s = 0; s < KT; s++) {
        int buf = s & 1;
        asm volatile("cp.async.wait_group 0;\n" ::: "memory");
        __syncthreads();    // data(s) ready in all warps; compute(s-1) done everywhere

        if (s + 1 < KT) copy_stage(s + 1, buf ^ 1);

#pragma unroll
        for (int kk = 0; kk < 2; kk++) {
            uint32_t koff = (uint32_t)(kk * 32);   // 16 halves = 32 bytes
            uint32_t a[4][4], b[4][2];
#pragma unroll
            for (int mi = 0; mi < 4; mi++) ldsm_x4(a[mi], sA[buf] + offA[mi] + koff);
#pragma unroll
            for (int ni = 0; ni < 4; ni++) ldsm_x2(b[ni], sB[buf] + offB[ni] + koff);
#pragma unroll
            for (int mi = 0; mi < 4; mi++)
#pragma unroll
                for (int ni = 0; ni < 4; ni++)
                    mma_f16(acc[mi][ni], a[mi], b[ni]);
        }
    }

    __syncthreads();  // all compute done before epilogue (no buffer hazard, but cheap)

    // epilogue (C fragment: lane -> rows grp/grp+8, cols 2*tig, 2*tig+1)
#pragma unroll
    for (int mi = 0; mi < 4; mi++) {
        int r0 = bm + wm + mi * 16 + grp;
#pragma unroll
        for (int ni = 0; ni < 4; ni++) {
            int c0 = bn + wn + ni * 8 + 2 * tig;
            float v00 = acc[mi][ni][0], v01 = acc[mi][ni][1];
            float v10 = acc[mi][ni][2], v11 = acc[mi][ni][3];
            if (bias) {
                float b0 = bias[c0], b1 = bias[c0 + 1];
                v00 += b0; v01 += b1; v10 += b0; v11 += b1;
            }
            if (MODE == 1) {
                float2 r1 = *(const float2*)(res + (size_t)r0 * N + c0);
                float2 r2 = *(const float2*)(res + (size_t)(r0 + 8) * N + c0);
                v00 += r1.x; v01 += r1.y; v10 += r2.x; v11 += r2.y;
            }
            if (MODE == 2) {
                __half2* o1 = (__half2*)((__half*)out + (size_t)r0 * N + c0);
                __half2* o2 = (__half2*)((__half*)out + (size_t)(r0 + 8) * N + c0);
                *o1 = __floats2half2_rn(gelu_f(v00), gelu_f(v01));
                *o2 = __floats2half2_rn(gelu_f(v10), gelu_f(v11));
            } else {
                float* op = (float*)out;
                *(float2*)(op + (size_t)r0 * N + c0) = make_float2(v00, v01);
                *(float2*)(op + (size_t)(r0 + 8) * N + c0) = make_float2(v10, v11);
            }
        }
    }
}

// ------------------------------------------------------------------
// Flash attention (SIMT, packed f32x2 math): fp32 qkv in, fp16 y out.
// One block = 256 queries of one (b,h); one thread = one query.
// ------------------------------------------------------------------
#define ATQ 256
#define ATK 64

__global__ __launch_bounds__(256) void attn_flash(const float* __restrict__ qkv,
                                                  __half* __restrict__ y) {
    int qi = blockIdx.x, h = blockIdx.y, b = blockIdx.z;
    int qbase = qi * ATQ;
    int tid = threadIdx.x;
    int q = qbase + tid;
    size_t rowbase = (size_t)b * Tc;

    __shared__ float Ks[ATK][32];
    __shared__ float Vs[ATK][32];

    // query into 16 packed f32x2 registers
    ull q2[16];
    {
        const ulonglong2* qp = (const ulonglong2*)(qkv + (rowbase + q) * (3 * Cc) + h * Dh);
#pragma unroll
        for (int j = 0; j < 8; j++) {
            ulonglong2 u = qp[j];
            q2[2 * j] = u.x;
            q2[2 * j + 1] = u.y;
        }
    }

    ull o2[16];
    const ull zz = pack2(0.f, 0.f);
#pragma unroll
    for (int j = 0; j < 16; j++) o2[j] = zz;
    float m = -INFINITY, l = 0.f;

    const float scale = 0.17677669529663687f;
    int nkt = (qbase + ATQ) / ATK;

    for (int kt = 0; kt < nkt; kt++) {
        int kbase = kt * ATK;
        bool masked = (kbase >= qbase);

        __syncthreads();
#pragma unroll
        for (int j = 0; j < 2; j++) {
            int i = tid + j * 256;
            int r = i >> 3, c = i & 7;
            const float* krow = qkv + (rowbase + kbase + r) * (3 * Cc) + Cc + h * Dh;
            const float* vrow = qkv + (rowbase + kbase + r) * (3 * Cc) + 2 * Cc + h * Dh;
            ((float4*)Ks[r])[c] = ((const float4*)krow)[c];
            ((float4*)Vs[r])[c] = ((const float4*)vrow)[c];
        }
        __syncthreads();

#pragma unroll 1
        for (int c0 = 0; c0 < ATK; c0 += 16) {
            float s[16];
#pragma unroll
            for (int kk = 0; kk < 16; kk++) {
                const ulonglong2* kr = (const ulonglong2*)Ks[c0 + kk];
                ull acc_a = zz, acc_b = zz;
#pragma unroll
                for (int j = 0; j < 8; j++) {
                    ulonglong2 kv = kr[j];
                    FMA2(acc_a, q2[2 * j], kv.x, acc_a);
                    FMA2(acc_b, q2[2 * j + 1], kv.y, acc_b);
                }
                float a0, a1, b0, b1;
                unpack2(acc_a, a0, a1);
                unpack2(acc_b, b0, b1);
                float acc = (a0 + b0) + (a1 + b1);
                int key = kbase + c0 + kk;
                s[kk] = (!masked || key <= q) ? acc * scale : -INFINITY;
            }

            float cm = s[0];
#pragma unroll
            for (int kk = 1; kk < 16; kk++) cm = fmaxf(cm, s[kk]);

            if (cm > m) {
                float alpha = __expf(m - cm);   // exp(-inf)=0 on first update
                l *= alpha;
                ull al2 = pack2(alpha, alpha);
#pragma unroll
                for (int j = 0; j < 16; j++) MUL2(o2[j], o2[j], al2);
                m = cm;
            }

#pragma unroll
            for (int kk = 0; kk < 16; kk++) {
                float p = __expf(s[kk] - m);    // masked -> 0
                l += p;
                ull p2 = pack2(p, p);
                const ulonglong2* vr = (const ulonglong2*)Vs[c0 + kk];
#pragma unroll
                for (int j = 0; j < 8; j++) {
                    ulonglong2 vv = vr[j];
                    FMA2(o2[2 * j], p2, vv.x, o2[2 * j]);
                    FMA2(o2[2 * j + 1], p2, vv.y, o2[2 * j + 1]);
                }
            }
        }
    }

    float inv = 1.0f / l;
    __half2* yp = (__half2*)(y + (rowbase + q) * Cc + h * Dh);
#pragma unroll
    for (int j = 0; j < 16; j++) {
        float lo, hi;
        unpack2(o2[j], lo, hi);
        yp[j] = __floats2half2_rn(lo * inv, hi * inv);
    }
}

// ------------------------------------------------------------------
// Host orchestration
// ------------------------------------------------------------------
extern "C" void kernel_launch(void* const* d_in, const int* in_sizes, int n_in,
                              void* d_out, int out_size) {
    const int*   idx    = (const int*)d_in[0];
    const float* tok    = (const float*)d_in[1];
    const float* pos    = (const float*)d_in[2];
    const float* ln1_g  = (const float*)d_in[3];
    const float* ln1_b  = (const float*)d_in[4];
    const float* wqkv   = (const float*)d_in[5];
    const float* bqkv   = (const float*)d_in[6];
    const float* wo     = (const float*)d_in[7];
    const float* bo     = (const float*)d_in[8];
    const float* ln2_g  = (const float*)d_in[9];
    const float* ln2_b  = (const float*)d_in[10];
    const float* wfc    = (const float*)d_in[11];
    const float* bfc    = (const float*)d_in[12];
    const float* wpr    = (const float*)d_in[13];
    const float* bpr    = (const float*)d_in[14];
    const float* lnf_g  = (const float*)d_in[15];
    const float* lnf_b  = (const float*)d_in[16];
    const float* w_lm   = (const float*)d_in[17];
    float* out = (float*)d_out;

    float *px, *pqkv;
    __half *ph256, *ph1024, *pwh;
    cudaGetSymbolAddress((void**)&px, g_x);
    cudaGetSymbolAddress((void**)&pqkv, g_qkv);
    cudaGetSymbolAddress((void**)&ph256, g_h256);
    cudaGetSymbolAddress((void**)&ph1024, g_h1024);
    cudaGetSymbolAddress((void**)&pwh, g_wh);

    __half* cw_qkv = pwh + W_QKV_OFF;
    __half* cw_o   = pwh + W_O_OFF;
    __half* cw_fc  = pwh + W_FC_OFF;
    __half* cw_pr  = pwh + W_PR_OFF;
    __half* cw_lm  = pwh + W_LM_OFF;

    cudaFuncSetAttribute(gemm_h<0, float>, cudaFuncAttributeMaxDynamicSharedMemorySize, SMEM_GEMM);
    cudaFuncSetAttribute(gemm_h<1, float>, cudaFuncAttributeMaxDynamicSharedMemorySize, SMEM_GEMM);
    cudaFuncSetAttribute(gemm_h<2, __half>, cudaFuncAttributeMaxDynamicSharedMemorySize, SMEM_GEMM);

    dim3 tb(32, 8);
    cvtT_kernel<<<dim3(768 / 32, 256 / 32, Lc), tb>>>(wqkv, cw_qkv, 256, 768);
    cvtT_kernel<<<dim3(256 / 32, 256 / 32, Lc), tb>>>(wo,   cw_o,   256, 256);
    cvtT_kernel<<<dim3(1024 / 32, 256 / 32, Lc), tb>>>(wfc, cw_fc,  256, 1024);
    cvtT_kernel<<<dim3(256 / 32, 1024 / 32, Lc), tb>>>(wpr, cw_pr,  1024, 256);
    cvtT_kernel<<<dim3(128 / 32, 256 / 32, 1), tb>>>(w_lm,  cw_lm,  256, 128);

    embed_kernel<<<NTOK, Cc>>>(idx, tok, pos, px);

    for (int l = 0; l < Lc; l++) {
        const __half* Wq = cw_qkv + (size_t)l * Cc * 3 * Cc;
        const float*  bq = bqkv + (size_t)l * 3 * Cc;
        const __half* Wo = cw_o + (size_t)l * Cc * Cc;
        const float*  bo_ = bo + (size_t)l * Cc;
        const __half* Wf = cw_fc + (size_t)l * Cc * FFc;
        const float*  bf = bfc + (size_t)l * FFc;
        const __half* Wp = cw_pr + (size_t)l * FFc * Cc;
        const float*  bp = bpr + (size_t)l * Cc;

        ln_kernel<<<NTOK, Cc>>>(px, ln1_g + (size_t)l * Cc, ln1_b + (size_t)l * Cc, ph256);
        {   // qkv = ln @ Wq + bq   [32768, 768] fp32
            dim3 grid((3 * Cc) / BN, NTOK / BM);
            gemm_h<0, float><<<grid, 256, SMEM_GEMM>>>(ph256, Wq, bq, nullptr, pqkv, NTOK, 3 * Cc, Cc);
        }
        {   // attention -> y (fp16) into ph256
            dim3 grid(Tc / ATQ, Hc, Bc);
            attn_flash<<<grid, 256>>>(pqkv, ph256);
        }
        {   // x = x + y @ Wo + bo  (fp32)
            dim3 grid(Cc / BN, NTOK / BM);
            gemm_h<1, float><<<grid, 256, SMEM_GEMM>>>(ph256, Wo, bo_, px, px, NTOK, Cc, Cc);
        }
        ln_kernel<<<NTOK, Cc>>>(px, ln2_g + (size_t)l * Cc, ln2_b + (size_t)l * Cc, ph256);
        {   // ff = gelu(ln @ Wf + bf)  [32768, 1024] fp16
            dim3 grid(FFc / BN, NTOK / BM);
            gemm_h<2, __half><<<grid, 256, SMEM_GEMM>>>(ph256, Wf, bf, nullptr, ph1024, NTOK, FFc, Cc);
        }
        {   // x = x + ff @ Wp + bp  (fp32)
            dim3 grid(Cc / BN, NTOK / BM);
            gemm_h<1, float><<<grid, 256, SMEM_GEMM>>>(ph1024, Wp, bp, px, px, NTOK, Cc, FFc);
        }
    }

    ln_kernel<<<NTOK, Cc>>>(px, lnf_g, lnf_b, ph256);
    {   // logits = ln @ w_lm  [32768, 128] fp32
        dim3 grid(Vc / BN, NTOK / BM);
        gemm_h<0, float><<<grid, 256, SMEM_GEMM>>>(ph256, cw_lm, nullptr, nullptr, out, NTOK, Vc, Cc);
    }
}

// round 12
// speedup vs baseline: 5.0900x; 1.0051x over previous
#include <cuda_runtime.h>
#include <cuda_fp16.h>
#include <math.h>
#include <stdint.h>

// ---- problem constants (gpt-small) ----
#define Lc 8
#define Hc 8
#define Cc 256
#define Vc 128
#define Tc 1024
#define Bc 32
#define Dh 32
#define FFc 1024
#define NTOK (Bc * Tc)   // 32768

typedef unsigned long long ull;

// ---- scratch (device globals; no allocation allowed) ----
__device__ float g_x[(size_t)NTOK * Cc];         // residual stream (fp32)
__device__ float g_qkv[(size_t)NTOK * 3 * Cc];   // qkv (fp32)
__device__ __half g_h256[(size_t)NTOK * Cc];     // half activations: ln / attn-y
__device__ __half g_h1024[(size_t)NTOK * FFc];   // half activations: gelu(ff)

// fp16 TRANSPOSED weights ([N,K] row-major): qkv | wo | wfc | wpr | w_lm
#define W_QKV_OFF 0
#define W_O_OFF   (W_QKV_OFF + (size_t)Lc * Cc * 3 * Cc)
#define W_FC_OFF  (W_O_OFF   + (size_t)Lc * Cc * Cc)
#define W_PR_OFF  (W_FC_OFF  + (size_t)Lc * Cc * FFc)
#define W_LM_OFF  (W_PR_OFF  + (size_t)Lc * FFc * Cc)
#define W_TOTAL   (W_LM_OFF  + (size_t)Cc * Vc)
__device__ __half g_wh[W_TOTAL];

// ------------------------------------------------------------------
// helpers
// ------------------------------------------------------------------
__device__ __forceinline__ float gelu_f(float x) {
    float x3 = x * x * x;
    return 0.5f * x * (1.0f + tanhf(0.7978845608028654f * (x + 0.044715f * x3)));
}

__device__ __forceinline__ uint32_t smem_u32(const void* p) {
    uint32_t a;
    asm("{.reg .u64 t; cvta.to.shared.u64 t, %1; cvt.u32.u64 %0, t;}" : "=r"(a) : "l"(p));
    return a;
}

__device__ __forceinline__ void cp16(uint32_t dst, const void* src) {
    asm volatile("cp.async.cg.shared.global [%0], [%1], 16;\n" :: "r"(dst), "l"(src));
}

__device__ __forceinline__ void mma_f16(float* c, const uint32_t* a, const uint32_t* b) {
    asm volatile(
        "mma.sync.aligned.m16n8k16.row.col.f32.f16.f16.f32 "
        "{%0,%1,%2,%3}, {%4,%5,%6,%7}, {%8,%9}, {%0,%1,%2,%3};\n"
        : "+f"(c[0]), "+f"(c[1]), "+f"(c[2]), "+f"(c[3])
        : "r"(a[0]), "r"(a[1]), "r"(a[2]), "r"(a[3]), "r"(b[0]), "r"(b[1]));
}

__device__ __forceinline__ void ldsm_x4(uint32_t* r, uint32_t addr) {
    asm volatile("ldmatrix.sync.aligned.m8n8.x4.shared.b16 {%0,%1,%2,%3}, [%4];"
                 : "=r"(r[0]), "=r"(r[1]), "=r"(r[2]), "=r"(r[3]) : "r"(addr));
}
__device__ __forceinline__ void ldsm_x2(uint32_t* r, uint32_t addr) {
    asm volatile("ldmatrix.sync.aligned.m8n8.x2.shared.b16 {%0,%1}, [%2];"
                 : "=r"(r[0]), "=r"(r[1]) : "r"(addr));
}

// packed f32x2 ops
__device__ __forceinline__ ull pack2(float lo, float hi) {
    ull r; asm("mov.b64 %0, {%1,%2};" : "=l"(r) : "f"(lo), "f"(hi)); return r;
}
__device__ __forceinline__ void unpack2(ull v, float& lo, float& hi) {
    asm("mov.b64 {%0,%1}, %2;" : "=f"(lo), "=f"(hi) : "l"(v));
}
#define FMA2(d, a, b, c) asm("fma.rn.f32x2 %0, %1, %2, %3;" : "=l"(d) : "l"(a), "l"(b), "l"(c))
#define MUL2(d, a, b)    asm("mul.rn.f32x2 %0, %1, %2;" : "=l"(d) : "l"(a), "l"(b))

// ------------------------------------------------------------------
// weight transpose + fp16 conversion: fp32 [K,N] -> fp16 [N,K]
// ------------------------------------------------------------------
__global__ void cvtT_kernel(const float* __restrict__ in, __half* __restrict__ out,
                            int K, int N) {
    __shared__ float t[32][33];
    int k0 = blockIdx.y * 32, n0 = blockIdx.x * 32;
    const float* src = in + (size_t)blockIdx.z * K * N;
    __half* dst = out + (size_t)blockIdx.z * K * N;
    int tx = threadIdx.x, ty = threadIdx.y;  // 32 x 8
#pragma unroll
    for (int i = 0; i < 4; i++)
        t[ty + 8 * i][tx] = src[(size_t)(k0 + ty + 8 * i) * N + n0 + tx];
    __syncthreads();
#pragma unroll
    for (int i = 0; i < 4; i++)
        dst[(size_t)(n0 + ty + 8 * i) * K + k0 + tx] = __float2half(t[tx][ty + 8 * i]);
}

// ------------------------------------------------------------------
// Embedding
// ------------------------------------------------------------------
__global__ void embed_kernel(const int* __restrict__ idx,
                             const float* __restrict__ tok,
                             const float* __restrict__ pos,
                             float* __restrict__ x) {
    int n = blockIdx.x;
    int c = threadIdx.x;
    int token = idx[n];
    x[(size_t)n * Cc + c] = tok[(size_t)token * Cc + c] + pos[(size_t)(n % Tc) * Cc + c];
}

// ------------------------------------------------------------------
// LayerNorm: fp32 in -> fp16 out
// ------------------------------------------------------------------
__global__ void ln_kernel(const float* __restrict__ x,
                          const float* __restrict__ g,
                          const float* __restrict__ b,
                          __half* __restrict__ out) {
    int row = blockIdx.x;
    int tid = threadIdx.x;
    int w = tid >> 5, lane = tid & 31;
    float v = x[(size_t)row * Cc + tid];

    __shared__ float sm[8];
    __shared__ float sm2[8];

    float s = v;
#pragma unroll
    for (int o = 16; o; o >>= 1) s += __shfl_xor_sync(0xffffffffu, s, o);
    if (lane == 0) sm[w] = s;
    __syncthreads();
    float tot = 0.f;
#pragma unroll
    for (int i = 0; i < 8; i++) tot += sm[i];
    float mean = tot * (1.0f / Cc);

    float d = v - mean;
    float q = d * d;
#pragma unroll
    for (int o = 16; o; o >>= 1) q += __shfl_xor_sync(0xffffffffu, q, o);
    if (lane == 0) sm2[w] = q;
    __syncthreads();
    float vtot = 0.f;
#pragma unroll
    for (int i = 0; i < 8; i++) vtot += sm2[i];
    float var = vtot * (1.0f / Cc);

    out[(size_t)row * Cc + tid] = __float2half(d * rsqrtf(var + 1e-5f) * g[tid] + b[tid]);
}

// ------------------------------------------------------------------
// fp16 tensor-core GEMM, 4-stage cp.async pipeline (wait_group 2).
// out[M,N] = A[M,K] @ Bt[N,K]^T (+bias)(+res)(+gelu)
// BM=128 BN=128 BK=32, 256 threads, 64x32 warp tile, m16n8k16, fp32 accum.
// MODE: 0=+bias->fp32, 1=+bias+res->fp32, 2=+bias+gelu->fp16
// ------------------------------------------------------------------
#define BM 128
#define BN 128
#define BK 32
#define NST 4
#define AST 40                       // halves per smem row (80B) - conflict-free ldmatrix
#define TILE_HALFS (128 * AST)       // 5120 halfs = 10240 B
#define STAGE_HALFS (2 * TILE_HALFS) // A+B per stage
#define SMEM_GEMM (NST * STAGE_HALFS * 2)   // 81920 bytes

template <int MODE, typename OutT>
__global__ __launch_bounds__(256, 2) void gemm_h(
    const __half* __restrict__ A, const __half* __restrict__ Bt,
    const float* __restrict__ bias, const float* __restrict__ res,
    OutT* __restrict__ out, int M, int N, int K) {
    extern __shared__ __half hsm[];

    int tid = threadIdx.x;
    int bm = blockIdx.y * BM;
    int bn = blockIdx.x * BN;
    int lane = tid & 31, wid = tid >> 5;
    int wm = (wid >> 2) * 64;   // warp M offset (0/64)
    int wn = (wid & 3) * 32;    // warp N offset (0/32/64/96)
    int grp = lane >> 2, tig = lane & 3;

    float acc[4][4][4];
#pragma unroll
    for (int i = 0; i < 4; i++)
#pragma unroll
        for (int j = 0; j < 4; j++)
#pragma unroll
            for (int k = 0; k < 4; k++) acc[i][j][k] = 0.f;

    uint32_t sA[NST], sB[NST];
#pragma unroll
    for (int i = 0; i < NST; i++) {
        sA[i] = smem_u32(hsm + i * STAGE_HALFS);
        sB[i] = sA[i] + TILE_HALFS * 2;   // bytes
    }

    // ldmatrix per-thread address offsets (bytes), buffer-independent
    uint32_t offA[4], offB[4];
    {
        int l16 = lane & 15;
        int ka = (lane >> 4) << 3;          // 0 or 8 halves
#pragma unroll
        for (int mi = 0; mi < 4; mi++)
            offA[mi] = (uint32_t)(((wm + mi * 16 + l16) * AST + ka) * 2);
        int l8 = lane & 7;
        int kb = ((lane >> 3) & 1) << 3;    // 0 or 8 halves
#pragma unroll
        for (int ni = 0; ni < 4; ni++)
            offB[ni] = (uint32_t)(((wn + ni * 8 + l8) * AST + kb) * 2);
    }

    int KT = K / BK;

    // copy one BK=32 stage (no commit inside)
    auto copy_stage = [&](int s, int buf) {
        int k0 = s * BK;
#pragma unroll
        for (int i = 0; i < 2; i++) {
            int id = tid + i * 256;        // 0..511
            int row = id >> 2;             // 0..127
            int ck = (id & 3) << 3;        // half-offset 0,8,16,24
            cp16(sA[buf] + (uint32_t)((row * AST + ck) * 2),
                 A + (size_t)(bm + row) * K + k0 + ck);
            cp16(sB[buf] + (uint32_t)((row * AST + ck) * 2),
                 Bt + (size_t)(bn + row) * K + k0 + ck);
        }
    };

    // prologue: stages 0..2 (K >= 128 always => KT >= 4)
#pragma unroll
    for (int s = 0; s < 3; s++) {
        copy_stage(s, s);
        asm volatile("cp.async.commit_group;\n" ::: "memory");
    }

    for (int s = 0; s < KT; s++) {
        int buf = s & (NST - 1);
        // group g_s (carrying stage s) is the (s+1)-th commit; with one commit
        // per iteration below, outstanding = 3 + s at this point, so
        // wait_group 2 guarantees g_s complete.
        asm volatile("cp.async.wait_group 2;\n" ::: "memory");
        __syncthreads();   // also: all warps done computing stage s-1 (buffer (s+3)&3)

        if (s + 3 < KT) copy_stage(s + 3, (s + 3) & (NST - 1));
        asm volatile("cp.async.commit_group;\n" ::: "memory");   // possibly empty group

#pragma unroll
        for (int kk = 0; kk < 2; kk++) {
            uint32_t koff = (uint32_t)(kk * 32);   // 16 halves = 32 bytes
            uint32_t a[4][4], b[4][2];
#pragma unroll
            for (int mi = 0; mi < 4; mi++) ldsm_x4(a[mi], sA[buf] + offA[mi] + koff);
#pragma unroll
            for (int ni = 0; ni < 4; ni++) ldsm_x2(b[ni], sB[buf] + offB[ni] + koff);
#pragma unroll
            for (int mi = 0; mi < 4; mi++)
#pragma unroll
                for (int ni = 0; ni < 4; ni++)
                    mma_f16(acc[mi][ni], a[mi], b[ni]);
        }
    }

    // epilogue (C fragment: lane -> rows grp/grp+8, cols 2*tig, 2*tig+1)
#pragma unroll
    for (int mi = 0; mi < 4; mi++) {
        int r0 = bm + wm + mi * 16 + grp;
#pragma unroll
        for (int ni = 0; ni < 4; ni++) {
            int c0 = bn + wn + ni * 8 + 2 * tig;
            float v00 = acc[mi][ni][0], v01 = acc[mi][ni][1];
            float v10 = acc[mi][ni][2], v11 = acc[mi][ni][3];
            if (bias) {
                float b0 = bias[c0], b1 = bias[c0 + 1];
                v00 += b0; v01 += b1; v10 += b0; v11 += b1;
            }
            if (MODE == 1) {
                float2 r1 = *(const float2*)(res + (size_t)r0 * N + c0);
                float2 r2 = *(const float2*)(res + (size_t)(r0 + 8) * N + c0);
                v00 += r1.x; v01 += r1.y; v10 += r2.x; v11 += r2.y;
            }
            if (MODE == 2) {
                __half2* o1 = (__half2*)((__half*)out + (size_t)r0 * N + c0);
                __half2* o2 = (__half2*)((__half*)out + (size_t)(r0 + 8) * N + c0);
                *o1 = __floats2half2_rn(gelu_f(v00), gelu_f(v01));
                *o2 = __floats2half2_rn(gelu_f(v10), gelu_f(v11));
            } else {
                float* op = (float*)out;
                *(float2*)(op + (size_t)r0 * N + c0) = make_float2(v00, v01);
                *(float2*)(op + (size_t)(r0 + 8) * N + c0) = make_float2(v10, v11);
            }
        }
    }
}

// ------------------------------------------------------------------
// Flash attention (SIMT, packed f32x2 math): fp32 qkv in, fp16 y out.
// ------------------------------------------------------------------
#define ATQ 256
#define ATK 64

__global__ __launch_bounds__(256) void attn_flash(const float* __restrict__ qkv,
                                                  __half* __restrict__ y) {
    int qi = blockIdx.x, h = blockIdx.y, b = blockIdx.z;
    int qbase = qi * ATQ;
    int tid = threadIdx.x;
    int q = qbase + tid;
    size_t rowbase = (size_t)b * Tc;

    __shared__ float Ks[ATK][32];
    __shared__ float Vs[ATK][32];

    ull q2[16];
    {
        const ulonglong2* qp = (const ulonglong2*)(qkv + (rowbase + q) * (3 * Cc) + h * Dh);
#pragma unroll
        for (int j = 0; j < 8; j++) {
            ulonglong2 u = qp[j];
            q2[2 * j] = u.x;
            q2[2 * j + 1] = u.y;
        }
    }

    ull o2[16];
    const ull zz = pack2(0.f, 0.f);
#pragma unroll
    for (int j = 0; j < 16; j++) o2[j] = zz;
    float m = -INFINITY, l = 0.f;

    const float scale = 0.17677669529663687f;
    int nkt = (qbase + ATQ) / ATK;

    for (int kt = 0; kt < nkt; kt++) {
        int kbase = kt * ATK;
        bool masked = (kbase >= qbase);

        __syncthreads();
#pragma unroll
        for (int j = 0; j < 2; j++) {
            int i = tid + j * 256;
            int r = i >> 3, c = i & 7;
            const float* krow = qkv + (rowbase + kbase + r) * (3 * Cc) + Cc + h * Dh;
            const float* vrow = qkv + (rowbase + kbase + r) * (3 * Cc) + 2 * Cc + h * Dh;
            ((float4*)Ks[r])[c] = ((const float4*)krow)[c];
            ((float4*)Vs[r])[c] = ((const float4*)vrow)[c];
        }
        __syncthreads();

#pragma unroll 1
        for (int c0 = 0; c0 < ATK; c0 += 16) {
            float s[16];
#pragma unroll
            for (int kk = 0; kk < 16; kk++) {
                const ulonglong2* kr = (const ulonglong2*)Ks[c0 + kk];
                ull acc_a = zz, acc_b = zz;
#pragma unroll
                for (int j = 0; j < 8; j++) {
                    ulonglong2 kv = kr[j];
                    FMA2(acc_a, q2[2 * j], kv.x, acc_a);
                    FMA2(acc_b, q2[2 * j + 1], kv.y, acc_b);
                }
                float a0, a1, b0, b1;
                unpack2(acc_a, a0, a1);
                unpack2(acc_b, b0, b1);
                float acc = (a0 + b0) + (a1 + b1);
                int key = kbase + c0 + kk;
                s[kk] = (!masked || key <= q) ? acc * scale : -INFINITY;
            }

            float cm = s[0];
#pragma unroll
            for (int kk = 1; kk < 16; kk++) cm = fmaxf(cm, s[kk]);

            if (cm > m) {
                float alpha = __expf(m - cm);
                l *= alpha;
                ull al2 = pack2(alpha, alpha);
#pragma unroll
                for (int j = 0; j < 16; j++) MUL2(o2[j], o2[j], al2);
                m = cm;
            }

#pragma unroll
            for (int kk = 0; kk < 16; kk++) {
                float p = __expf(s[kk] - m);
                l += p;
                ull p2 = pack2(p, p);
                const ulonglong2* vr = (const ulonglong2*)Vs[c0 + kk];
#pragma unroll
                for (int j = 0; j < 8; j++) {
                    ulonglong2 vv = vr[j];
                    FMA2(o2[2 * j], p2, vv.x, o2[2 * j]);
                    FMA2(o2[2 * j + 1], p2, vv.y, o2[2 * j + 1]);
                }
            }
        }
    }

    float inv = 1.0f / l;
    __half2* yp = (__half2*)(y + (rowbase + q) * Cc + h * Dh);
#pragma unroll
    for (int j = 0; j < 16; j++) {
        float lo, hi;
        unpack2(o2[j], lo, hi);
        yp[j] = __floats2half2_rn(lo * inv, hi * inv);
    }
}

// ------------------------------------------------------------------
// Host orchestration (launch order arranged so global launch #5 is the
// layer-0 qkv GEMM -> ncu -s 5 -c 1 finally profiles the dominant kernel)
// ------------------------------------------------------------------
extern "C" void kernel_launch(void* const* d_in, const int* in_sizes, int n_in,
                              void* d_out, int out_size) {
    const int*   idx    = (const int*)d_in[0];
    const float* tok    = (const float*)d_in[1];
    const float* pos    = (const float*)d_in[2];
    const float* ln1_g  = (const float*)d_in[3];
    const float* ln1_b  = (const float*)d_in[4];
    const float* wqkv   = (const float*)d_in[5];
    const float* bqkv   = (const float*)d_in[6];
    const float* wo     = (const float*)d_in[7];
    const float* bo     = (const float*)d_in[8];
    const float* ln2_g  = (const float*)d_in[9];
    const float* ln2_b  = (const float*)d_in[10];
    const float* wfc    = (const float*)d_in[11];
    const float* bfc    = (const float*)d_in[12];
    const float* wpr    = (const float*)d_in[13];
    const float* bpr    = (const float*)d_in[14];
    const float* lnf_g  = (const float*)d_in[15];
    const float* lnf_b  = (const float*)d_in[16];
    const float* w_lm   = (const float*)d_in[17];
    float* out = (float*)d_out;

    float *px, *pqkv;
    __half *ph256, *ph1024, *pwh;
    cudaGetSymbolAddress((void**)&px, g_x);
    cudaGetSymbolAddress((void**)&pqkv, g_qkv);
    cudaGetSymbolAddress((void**)&ph256, g_h256);
    cudaGetSymbolAddress((void**)&ph1024, g_h1024);
    cudaGetSymbolAddress((void**)&pwh, g_wh);

    __half* cw_qkv = pwh + W_QKV_OFF;
    __half* cw_o   = pwh + W_O_OFF;
    __half* cw_fc  = pwh + W_FC_OFF;
    __half* cw_pr  = pwh + W_PR_OFF;
    __half* cw_lm  = pwh + W_LM_OFF;

    cudaFuncSetAttribute(gemm_h<0, float>, cudaFuncAttributeMaxDynamicSharedMemorySize, SMEM_GEMM);
    cudaFuncSetAttribute(gemm_h<1, float>, cudaFuncAttributeMaxDynamicSharedMemorySize, SMEM_GEMM);
    cudaFuncSetAttribute(gemm_h<2, __half>, cudaFuncAttributeMaxDynamicSharedMemorySize, SMEM_GEMM);

    dim3 tb(32, 8);
    dim3 gemm_grid_qkv((3 * Cc) / BN, NTOK / BM);
    dim3 gemm_grid_c(Cc / BN, NTOK / BM);
    dim3 gemm_grid_ff(FFc / BN, NTOK / BM);
    dim3 attn_grid(Tc / ATQ, Hc, Bc);

    // --- launches 0..4: embed, cvt(qkv), ln1(l0), cvt(wo), cvt(wfc) ---
    embed_kernel<<<NTOK, Cc>>>(idx, tok, pos, px);                             // 0
    cvtT_kernel<<<dim3(768 / 32, 256 / 32, Lc), tb>>>(wqkv, cw_qkv, 256, 768); // 1
    ln_kernel<<<NTOK, Cc>>>(px, ln1_g, ln1_b, ph256);                          // 2
    cvtT_kernel<<<dim3(256 / 32, 256 / 32, Lc), tb>>>(wo, cw_o, 256, 256);     // 3
    cvtT_kernel<<<dim3(1024 / 32, 256 / 32, Lc), tb>>>(wfc, cw_fc, 256, 1024); // 4
    // --- launch 5: layer-0 qkv GEMM (ncu target) ---
    gemm_h<0, float><<<gemm_grid_qkv, 256, SMEM_GEMM>>>(ph256, cw_qkv, bqkv, nullptr,
                                                        pqkv, NTOK, 3 * Cc, Cc); // 5
    // remaining weight converts
    cvtT_kernel<<<dim3(256 / 32, 1024 / 32, Lc), tb>>>(wpr, cw_pr, 1024, 256); // 6
    cvtT_kernel<<<dim3(128 / 32, 256 / 32, 1), tb>>>(w_lm, cw_lm, 256, 128);   // 7

    for (int l = 0; l < Lc; l++) {
        const __half* Wq = cw_qkv + (size_t)l * Cc * 3 * Cc;
        const float*  bq = bqkv + (size_t)l * 3 * Cc;
        const __half* Wo = cw_o + (size_t)l * Cc * Cc;
        const float*  bo_ = bo + (size_t)l * Cc;
        const __half* Wf = cw_fc + (size_t)l * Cc * FFc;
        const float*  bf = bfc + (size_t)l * FFc;
        const __half* Wp = cw_pr + (size_t)l * FFc * Cc;
        const float*  bp = bpr + (size_t)l * Cc;

        if (l > 0) {
            ln_kernel<<<NTOK, Cc>>>(px, ln1_g + (size_t)l * Cc, ln1_b + (size_t)l * Cc, ph256);
            gemm_h<0, float><<<gemm_grid_qkv, 256, SMEM_GEMM>>>(ph256, Wq, bq, nullptr,
                                                                pqkv, NTOK, 3 * Cc, Cc);
        }
        attn_flash<<<attn_grid, 256>>>(pqkv, ph256);
        gemm_h<1, float><<<gemm_grid_c, 256, SMEM_GEMM>>>(ph256, Wo, bo_, px, px, NTOK, Cc, Cc);
        ln_kernel<<<NTOK, Cc>>>(px, ln2_g + (size_t)l * Cc, ln2_b + (size_t)l * Cc, ph256);
        gemm_h<2, __half><<<gemm_grid_ff, 256, SMEM_GEMM>>>(ph256, Wf, bf, nullptr,
                                                            ph1024, NTOK, FFc, Cc);
        gemm_h<1, float><<<gemm_grid_c, 256, SMEM_GEMM>>>(ph1024, Wp, bp, px, px, NTOK, Cc, FFc);
    }

    ln_kernel<<<NTOK, Cc>>>(px, lnf_g, lnf_b, ph256);
    {
        dim3 grid(Vc / BN, NTOK / BM);
        gemm_h<0, float><<<grid, 256, SMEM_GEMM>>>(ph256, cw_lm, nullptr, nullptr, out, NTOK, Vc, Cc);
    }
}